// round 1
// baseline (speedup 1.0000x reference)
#include <cuda_runtime.h>

#define NB 8
#define NS 128
#define ND 512
#define NL 512
#define NR 50
#define NBS 1024            // NB*NS
#define OUT_HEAD (NB*NS*NS) // 131072

// Projection scratch: [head*2+side][row=b*S+i][l]. side0 = left, side1 = right (+b1 folded).
__device__ float g_P[8][NBS][NL];

struct ProjArgs { const float* W1[4]; const float* b1[4]; };
struct ScalArgs { const float* w2[3]; const float* b2[3]; };

__device__ __forceinline__ float tanha(float x) {
    float y; asm("tanh.approx.f32 %0, %1;" : "=f"(y) : "f"(x)); return y;
}

union U64 { unsigned long long u; float2 f; };

__device__ __forceinline__ void ffma2(unsigned long long& d,
                                      unsigned long long a,
                                      unsigned long long b) {
    asm("fma.rn.f32x2 %0, %1, %2, %0;" : "+l"(d) : "l"(a), "l"(b));
}

// ---------------------------------------------------------------------------
// Kernel A: projections.  C[z] = X(1024x512) @ W1[head][side] (512x512), +b1 on side 1.
// Tile 128x64, k-chunk 32, 256 threads, 8x4 micro-tile.
// ---------------------------------------------------------------------------
__global__ __launch_bounds__(256) void proj_kernel(const float* __restrict__ x, ProjArgs pa) {
    const int z = blockIdx.z, head = z >> 1, side = z & 1;
    const float* __restrict__ W = pa.W1[head] + (side ? ND * NL : 0);
    const int r0 = blockIdx.x * 128, c0 = blockIdx.y * 64;
    __shared__ float Xs[128][33];
    __shared__ float Ws[32][64];
    const int t = threadIdx.x, tx = t & 15, ty = t >> 4;
    float acc[8][4];
#pragma unroll
    for (int r = 0; r < 8; r++) { acc[r][0]=0.f; acc[r][1]=0.f; acc[r][2]=0.f; acc[r][3]=0.f; }

    for (int k0 = 0; k0 < ND; k0 += 32) {
#pragma unroll
        for (int m = 0; m < 4; m++) {
            int e = t + 256 * m, row = e >> 3, c4 = (e & 7) << 2;
            float4 v = *(const float4*)(x + (r0 + row) * ND + k0 + c4);
            Xs[row][c4] = v.x; Xs[row][c4+1] = v.y; Xs[row][c4+2] = v.z; Xs[row][c4+3] = v.w;
        }
#pragma unroll
        for (int m = 0; m < 2; m++) {
            int e = t + 256 * m, kk = e >> 4, c4 = (e & 15) << 2;
            *(float4*)&Ws[kk][c4] = *(const float4*)(W + (k0 + kk) * NL + c0 + c4);
        }
        __syncthreads();
#pragma unroll
        for (int kk = 0; kk < 32; kk++) {
            float b4[4];
            *(float4*)b4 = *(const float4*)&Ws[kk][tx << 2];
#pragma unroll
            for (int r = 0; r < 8; r++) {
                float a = Xs[(ty << 3) + r][kk];
                acc[r][0] = fmaf(a, b4[0], acc[r][0]);
                acc[r][1] = fmaf(a, b4[1], acc[r][1]);
                acc[r][2] = fmaf(a, b4[2], acc[r][2]);
                acc[r][3] = fmaf(a, b4[3], acc[r][3]);
            }
        }
        __syncthreads();
    }
    float bias[4] = {0.f, 0.f, 0.f, 0.f};
    if (side) {
        const float* b1 = pa.b1[head];
#pragma unroll
        for (int c = 0; c < 4; c++) bias[c] = b1[c0 + (tx << 2) + c];
    }
    float* o = &g_P[z][0][0];
#pragma unroll
    for (int r = 0; r < 8; r++) {
        float4 v = make_float4(acc[r][0] + bias[0], acc[r][1] + bias[1],
                               acc[r][2] + bias[2], acc[r][3] + bias[3]);
        *(float4*)&o[(r0 + (ty << 3) + r) * NL + c0 + (tx << 2)] = v;
    }
}

// ---------------------------------------------------------------------------
// Kernel B: the three n_out=1 heads.  out[b,i,j] = sum_l tanh(L[i,l]+R[j,l])*w2[l] + b2.
// Block = (head, b, 32x32 ij-tile), 256 threads, 2x2 micro. Span (head 0) skips
// strictly-upper tiles (filled later by sym_kernel).
// ---------------------------------------------------------------------------
__global__ __launch_bounds__(256) void pair_scalar_kernel(ScalArgs sa, float* __restrict__ out) {
    const int head = blockIdx.z, b = blockIdx.y;
    const int jt = blockIdx.x & 3, it = blockIdx.x >> 2;
    if (head == 0 && it < jt) return;   // strictly above the diagonal: mirrored later
    const int i0 = it * 32, j0 = jt * 32;
    __shared__ float Ls[64][33], Rs[64][33];
    __shared__ float w2s[64];
    const float* __restrict__ Lg = &g_P[head * 2][b * NS + i0][0];
    const float* __restrict__ Rg = &g_P[head * 2 + 1][b * NS + j0][0];
    const float* __restrict__ w2 = sa.w2[head];
    const int t = threadIdx.x, tj = (t & 15) << 1, ti = (t >> 4) << 1;
    float a00 = 0.f, a01 = 0.f, a10 = 0.f, a11 = 0.f;

    for (int l0 = 0; l0 < NL; l0 += 64) {
#pragma unroll
        for (int m = 0; m < 8; m++) {
            int e = t + 256 * m, i = e >> 6, lk = e & 63;
            Ls[lk][i] = Lg[i * NL + l0 + lk];
            Rs[lk][i] = Rg[i * NL + l0 + lk];
        }
        if (t < 64) w2s[t] = w2[l0 + t];
        __syncthreads();
#pragma unroll
        for (int lk = 0; lk < 64; lk++) {
            float x0 = Ls[lk][ti], x1 = Ls[lk][ti + 1];
            float y0 = Rs[lk][tj], y1 = Rs[lk][tj + 1];
            float w = w2s[lk];
            a00 = fmaf(tanha(x0 + y0), w, a00);
            a01 = fmaf(tanha(x0 + y1), w, a01);
            a10 = fmaf(tanha(x1 + y0), w, a10);
            a11 = fmaf(tanha(x1 + y1), w, a11);
        }
        __syncthreads();
    }
    const float b2 = sa.b2[head][0];
    float* o = out + head * OUT_HEAD + b * NS * NS;
    o[(i0 + ti) * NS + j0 + tj]         = a00 + b2;
    o[(i0 + ti) * NS + j0 + tj + 1]     = a01 + b2;
    o[(i0 + ti + 1) * NS + j0 + tj]     = a10 + b2;
    o[(i0 + ti + 1) * NS + j0 + tj + 1] = a11 + b2;
}

// ---------------------------------------------------------------------------
// Kernel C: lab head (R=50).  Block = (b, 16 i x 8 j = 128 pairs) x 50 outputs.
// Per 32-l chunk: build H tile (tanh) in smem, then GEMM 128x50 += H(128x32)@W2(32x50)
// using packed fma.rn.f32x2 (2 pairs per instruction).
// ---------------------------------------------------------------------------
__global__ __launch_bounds__(256) void lab_kernel(const float* __restrict__ W2,
                                                  const float* __restrict__ b2,
                                                  float* __restrict__ out) {
    const int b = blockIdx.z, it = blockIdx.y, jt = blockIdx.x;
    const int i0 = it * 16, j0 = jt * 8;
    __shared__ float Ls[16][33], Rs[8][33];
    __shared__ float Hs[32][132];                    // [lk][pair], padded
    __shared__ unsigned long long W2d[32][56];       // (w,w) duplicated pairs, zero-padded o>=50
    const float* __restrict__ Lg = &g_P[6][b * NS + i0][0];
    const float* __restrict__ Rg = &g_P[7][b * NS + j0][0];
    const int t = threadIdx.x, og = t & 7, pg = t >> 3;  // og: 7 outputs each; pg: 4 pairs each

    unsigned long long acc2[2][7];
#pragma unroll
    for (int q = 0; q < 2; q++)
#pragma unroll
        for (int c = 0; c < 7; c++) acc2[q][c] = 0ull;

    for (int l0 = 0; l0 < NL; l0 += 32) {
#pragma unroll
        for (int m = 0; m < 2; m++) {
            int e = t + 256 * m, i = e >> 5, lk = e & 31;
            Ls[i][lk] = Lg[i * NL + l0 + lk];
        }
        { int j = t >> 5, lk = t & 31; Rs[j][lk] = Rg[j * NL + l0 + lk]; }
#pragma unroll
        for (int m = 0; m < 7; m++) {
            int e = t + 256 * m;
            int lk = e / 56, oo = e - lk * 56;
            float w = (oo < NR) ? W2[(l0 + lk) * NR + oo] : 0.f;
            U64 u; u.f = make_float2(w, w);
            W2d[lk][oo] = u.u;
        }
        __syncthreads();
        // H tile: 128 pairs x 32 l
#pragma unroll
        for (int m = 0; m < 16; m++) {
            int e = t + 256 * m, p = e & 127, lk = e >> 7;
            Hs[lk][p] = tanha(Ls[p >> 3][lk] + Rs[p & 7][lk]);
        }
        __syncthreads();
        // GEMM with packed f32x2
#pragma unroll
        for (int lk = 0; lk < 32; lk++) {
            unsigned long long h01 = *(const unsigned long long*)&Hs[lk][pg << 2];
            unsigned long long h23 = *(const unsigned long long*)&Hs[lk][(pg << 2) + 2];
#pragma unroll
            for (int c = 0; c < 7; c++) {
                unsigned long long w = W2d[lk][og * 7 + c];
                ffma2(acc2[0][c], h01, w);
                ffma2(acc2[1][c], h23, w);
            }
        }
        __syncthreads();
    }
    // epilogue
#pragma unroll
    for (int c = 0; c < 7; c++) {
        int o = og * 7 + c;
        if (o < NR) {
            float bv = b2[o];
#pragma unroll
            for (int q = 0; q < 4; q++) {
                U64 u; u.u = acc2[q >> 1][c];
                float v = (q & 1) ? u.f.y : u.f.x;
                int p = (pg << 2) + q;
                int i = i0 + (p >> 3), j = j0 + (p & 7);
                out[((b * NS + i) * NS + j) * NR + o] = v + bv;
            }
        }
    }
}

// ---------------------------------------------------------------------------
// Kernel D: span symmetrization. final[b,i,j] = raw[b,max(i,j),min(i,j)]:
// copy lower triangle over upper.
// ---------------------------------------------------------------------------
__global__ void sym_kernel(float* __restrict__ out) {
    int idx = blockIdx.x * 256 + threadIdx.x;
    int b = idx >> 14, r = idx & 16383, i = r >> 7, j = r & 127;
    if (i < j) out[idx] = out[(b << 14) + (j << 7) + i];
}

// ---------------------------------------------------------------------------
extern "C" void kernel_launch(void* const* d_in, const int* in_sizes, int n_in,
                              void* d_out, int out_size) {
    (void)in_sizes; (void)n_in; (void)out_size;
    const float* x = (const float*)d_in[0];

    ProjArgs pa;
    pa.W1[0] = (const float*)d_in[1];  pa.b1[0] = (const float*)d_in[2];
    pa.W1[1] = (const float*)d_in[5];  pa.b1[1] = (const float*)d_in[6];
    pa.W1[2] = (const float*)d_in[9];  pa.b1[2] = (const float*)d_in[10];
    pa.W1[3] = (const float*)d_in[13]; pa.b1[3] = (const float*)d_in[14];
    proj_kernel<<<dim3(8, 8, 8), 256>>>(x, pa);

    float* out = (float*)d_out;
    ScalArgs sa;
    sa.w2[0] = (const float*)d_in[3];  sa.b2[0] = (const float*)d_in[4];
    sa.w2[1] = (const float*)d_in[7];  sa.b2[1] = (const float*)d_in[8];
    sa.w2[2] = (const float*)d_in[11]; sa.b2[2] = (const float*)d_in[12];
    pair_scalar_kernel<<<dim3(16, 8, 3), 256>>>(sa, out);

    lab_kernel<<<dim3(16, 8, 8), 256>>>((const float*)d_in[15], (const float*)d_in[16],
                                        out + 3 * OUT_HEAD);

    sym_kernel<<<512, 256>>>(out);
}

// round 2
// speedup vs baseline: 1.0826x; 1.0826x over previous
#include <cuda_runtime.h>

#define NB 8
#define NS 128
#define ND 512
#define NL 512
#define NR 50
#define NBS 1024            // NB*NS
#define OUT_HEAD (NB*NS*NS) // 131072

// Projection scratch: [head*2+side][row=b*S+i][l]. side0 = left, side1 = right (+b1 folded).
__device__ float g_P[8][NBS][NL];

struct ProjArgs { const float* W1[4]; const float* b1[4]; };
struct ScalArgs { const float* w2[3]; const float* b2[3]; };

typedef unsigned long long ULL;
union U64 { ULL u; float2 f; };

__device__ __forceinline__ float tanha(float x) {
    float y; asm("tanh.approx.f32 %0, %1;" : "=f"(y) : "f"(x)); return y;
}
__device__ __forceinline__ void ffma2(ULL& d, ULL a, ULL b) {
    asm("fma.rn.f32x2 %0, %1, %2, %0;" : "+l"(d) : "l"(a), "l"(b));
}
__device__ __forceinline__ ULL pack2(float lo, float hi) {
    ULL u;
    asm("mov.b64 %0, {%1, %2};" : "=l"(u) : "r"(__float_as_uint(lo)), "r"(__float_as_uint(hi)));
    return u;
}

// ---------------------------------------------------------------------------
// Kernel A: projections.  C[z] = X(1024x512) @ W1[head][side] (512x512), +b1 on side 1.
// Tile 128x64, k-chunk 32, 256 threads, 8x4 micro-tile, packed f32x2 FMA.
// ---------------------------------------------------------------------------
__global__ __launch_bounds__(256) void proj_kernel(const float* __restrict__ x, ProjArgs pa) {
    const int z = blockIdx.z, head = z >> 1, side = z & 1;
    const float* __restrict__ W = pa.W1[head] + (side ? ND * NL : 0);
    const int r0 = blockIdx.x * 128, c0 = blockIdx.y * 64;
    __shared__ float Xs[128][33];
    __shared__ float Ws[32][64];
    const int t = threadIdx.x, tx = t & 15, ty = t >> 4;
    ULL acc2[8][2];
#pragma unroll
    for (int r = 0; r < 8; r++) { acc2[r][0] = 0ull; acc2[r][1] = 0ull; }

    for (int k0 = 0; k0 < ND; k0 += 32) {
#pragma unroll
        for (int m = 0; m < 4; m++) {
            int e = t + 256 * m, row = e >> 3, c4 = (e & 7) << 2;
            float4 v = *(const float4*)(x + (r0 + row) * ND + k0 + c4);
            Xs[row][c4] = v.x; Xs[row][c4+1] = v.y; Xs[row][c4+2] = v.z; Xs[row][c4+3] = v.w;
        }
#pragma unroll
        for (int m = 0; m < 2; m++) {
            int e = t + 256 * m, kk = e >> 4, c4 = (e & 15) << 2;
            *(float4*)&Ws[kk][c4] = *(const float4*)(W + (k0 + kk) * NL + c0 + c4);
        }
        __syncthreads();
#pragma unroll
        for (int kk = 0; kk < 32; kk++) {
            float4 bv = *(const float4*)&Ws[kk][tx << 2];
            ULL b01 = pack2(bv.x, bv.y);
            ULL b23 = pack2(bv.z, bv.w);
#pragma unroll
            for (int r = 0; r < 8; r++) {
                float a = Xs[(ty << 3) + r][kk];
                ULL aa = pack2(a, a);
                ffma2(acc2[r][0], aa, b01);
                ffma2(acc2[r][1], aa, b23);
            }
        }
        __syncthreads();
    }
    float bias[4] = {0.f, 0.f, 0.f, 0.f};
    if (side) {
        const float* b1 = pa.b1[head];
#pragma unroll
        for (int c = 0; c < 4; c++) bias[c] = b1[c0 + (tx << 2) + c];
    }
    float* o = &g_P[z][0][0];
#pragma unroll
    for (int r = 0; r < 8; r++) {
        U64 u0, u1; u0.u = acc2[r][0]; u1.u = acc2[r][1];
        float4 v = make_float4(u0.f.x + bias[0], u0.f.y + bias[1],
                               u1.f.x + bias[2], u1.f.y + bias[3]);
        *(float4*)&o[(r0 + (ty << 3) + r) * NL + c0 + (tx << 2)] = v;
    }
}

// ---------------------------------------------------------------------------
// Kernel B: the three n_out=1 heads.  out[b,i,j] = sum_l tanh(L[i,l]+R[j,l])*w2[l] + b2.
// Block = (head, b, 64i x 32j tile), 256 threads, 4x2 micro (8 tanh per lk per thread).
// Span (head 0) skips tiles strictly above the diagonal (filled later by sym_kernel).
// ---------------------------------------------------------------------------
__global__ __launch_bounds__(256) void pair_scalar_kernel(ScalArgs sa, float* __restrict__ out) {
    const int head = blockIdx.z, b = blockIdx.y;
    const int it = blockIdx.x >> 2, jt = blockIdx.x & 3;
    if (head == 0 && it * 64 + 63 < jt * 32) return;   // strictly upper: mirrored later
    const int i0 = it * 64, j0 = jt * 32;
    __shared__ float Ls[32][68];   // [lk][i], 272B rows (16B aligned), 4-way STS conflict ok
    __shared__ float Rs[32][36];   // [lk][j]
    __shared__ float w2s[32];
    const float* __restrict__ Lg = &g_P[head * 2][b * NS + i0][0];
    const float* __restrict__ Rg = &g_P[head * 2 + 1][b * NS + j0][0];
    const float* __restrict__ w2 = sa.w2[head];
    const int t = threadIdx.x;
    const int ti4 = (t >> 4) << 2;     // 16 i-groups of 4
    const int tj2 = (t & 15) << 1;     // 16 j-groups of 2
    float acc[4][2];
#pragma unroll
    for (int r = 0; r < 4; r++) { acc[r][0] = 0.f; acc[r][1] = 0.f; }

    for (int l0 = 0; l0 < NL; l0 += 32) {
#pragma unroll
        for (int m = 0; m < 8; m++) {        // 64 rows x 32 lk
            int e = t + 256 * m, lk = e & 31, i = e >> 5;
            Ls[lk][i] = Lg[i * NL + l0 + lk];
        }
#pragma unroll
        for (int m = 0; m < 4; m++) {        // 32 rows x 32 lk
            int e = t + 256 * m, lk = e & 31, j = e >> 5;
            Rs[lk][j] = Rg[j * NL + l0 + lk];
        }
        if (t < 32) w2s[t] = w2[l0 + t];
        __syncthreads();
#pragma unroll
        for (int lk = 0; lk < 32; lk++) {
            float4 xv = *(const float4*)&Ls[lk][ti4];
            float2 yv = *(const float2*)&Rs[lk][tj2];
            float w = w2s[lk];
            float xs[4] = {xv.x, xv.y, xv.z, xv.w};
#pragma unroll
            for (int r = 0; r < 4; r++) {
                acc[r][0] = fmaf(tanha(xs[r] + yv.x), w, acc[r][0]);
                acc[r][1] = fmaf(tanha(xs[r] + yv.y), w, acc[r][1]);
            }
        }
        __syncthreads();
    }
    const float b2 = sa.b2[head][0];
    float* o = out + head * OUT_HEAD + b * NS * NS;
#pragma unroll
    for (int r = 0; r < 4; r++) {
        o[(i0 + ti4 + r) * NS + j0 + tj2]     = acc[r][0] + b2;
        o[(i0 + ti4 + r) * NS + j0 + tj2 + 1] = acc[r][1] + b2;
    }
}

// ---------------------------------------------------------------------------
// Kernel C: lab head (R=50).  Block = (b, 32i x 8j = 256 pairs).
// Per 16-l chunk: build H tile (tanh) in smem, then 256x56 += H(256x16)@W2dup(16x56)
// with packed fma.rn.f32x2. Thread owns 8 pairs (1 i-row, all 8 j) x 7 outputs.
// ---------------------------------------------------------------------------
#define LCH 16
__global__ __launch_bounds__(256) void lab_kernel(const float* __restrict__ W2,
                                                  const float* __restrict__ b2,
                                                  float* __restrict__ out) {
    const int b = blockIdx.z, it = blockIdx.y, jt = blockIdx.x;
    const int i0 = it * 32, j0 = jt * 8;
    __shared__ float Ls[32][LCH + 1];          // [i][lk]
    __shared__ float Rs[8][LCH + 1];           // [j][lk]
    __shared__ float Hs[LCH][264];             // [lk][pair]; pair = i*8+j
    __shared__ ULL   W2d[LCH][57];             // duplicated (w,w) pairs, zero-padded o>=50
    const float* __restrict__ Lg = &g_P[6][b * NS + i0][0];
    const float* __restrict__ Rg = &g_P[7][b * NS + j0][0];
    const int t = threadIdx.x, og = t & 7, pgrp = t >> 3;  // og: 7 outs; pgrp: i-row, 8 pairs

    ULL acc2[4][7];
#pragma unroll
    for (int q = 0; q < 4; q++)
#pragma unroll
        for (int c = 0; c < 7; c++) acc2[q][c] = 0ull;

    for (int l0 = 0; l0 < NL; l0 += LCH) {
#pragma unroll
        for (int m = 0; m < 2; m++) {          // 32 i x 16 lk = 512
            int e = t + 256 * m, i = e >> 4, lk = e & 15;
            Ls[i][lk] = Lg[i * NL + l0 + lk];
        }
        if (t < 128) { int j = t >> 4, lk = t & 15; Rs[j][lk] = Rg[j * NL + l0 + lk]; }
#pragma unroll
        for (int m = 0; m < 4; m++) {          // 16 lk x 56 outs = 896
            int e = t + 256 * m;
            if (e < LCH * 56) {
                int lk = e / 56, oo = e - lk * 56;
                float w = (oo < NR) ? W2[(l0 + lk) * NR + oo] : 0.f;
                W2d[lk][oo] = pack2(w, w);
            }
        }
        __syncthreads();
        // H tile: 16 lk x 256 pairs
#pragma unroll
        for (int m = 0; m < LCH; m++) {
            int e = t + 256 * m, lk = e >> 8, p = e & 255;
            Hs[lk][p] = tanha(Ls[p >> 3][lk] + Rs[p & 7][lk]);
        }
        __syncthreads();
        // GEMM with packed f32x2
#pragma unroll
        for (int lk = 0; lk < LCH; lk++) {
            ULL h[4];
#pragma unroll
            for (int q = 0; q < 4; q++)
                h[q] = *(const ULL*)&Hs[lk][pgrp * 8 + q * 2];
#pragma unroll
            for (int c = 0; c < 7; c++) {
                ULL w = W2d[lk][og * 7 + c];
#pragma unroll
                for (int q = 0; q < 4; q++) ffma2(acc2[q][c], h[q], w);
            }
        }
        __syncthreads();
    }
    // epilogue: thread's pairs are (i = i0+pgrp, j = j0 + 2q+k)
#pragma unroll
    for (int c = 0; c < 7; c++) {
        int o = og * 7 + c;
        if (o < NR) {
            float bv = b2[o];
            float* obase = out + ((b * NS + i0 + pgrp) * NS + j0) * NR + o;
#pragma unroll
            for (int q = 0; q < 4; q++) {
                U64 u; u.u = acc2[q][c];
                obase[(2 * q) * NR]     = u.f.x + bv;
                obase[(2 * q + 1) * NR] = u.f.y + bv;
            }
        }
    }
}

// ---------------------------------------------------------------------------
// Kernel D: span symmetrization. final[b,i,j] = raw[b,max(i,j),min(i,j)]:
// copy lower triangle over upper.
// ---------------------------------------------------------------------------
__global__ void sym_kernel(float* __restrict__ out) {
    int idx = blockIdx.x * 256 + threadIdx.x;
    int b = idx >> 14, r = idx & 16383, i = r >> 7, j = r & 127;
    if (i < j) out[idx] = out[(b << 14) + (j << 7) + i];
}

// ---------------------------------------------------------------------------
extern "C" void kernel_launch(void* const* d_in, const int* in_sizes, int n_in,
                              void* d_out, int out_size) {
    (void)in_sizes; (void)n_in; (void)out_size;
    const float* x = (const float*)d_in[0];

    ProjArgs pa;
    pa.W1[0] = (const float*)d_in[1];  pa.b1[0] = (const float*)d_in[2];
    pa.W1[1] = (const float*)d_in[5];  pa.b1[1] = (const float*)d_in[6];
    pa.W1[2] = (const float*)d_in[9];  pa.b1[2] = (const float*)d_in[10];
    pa.W1[3] = (const float*)d_in[13]; pa.b1[3] = (const float*)d_in[14];
    proj_kernel<<<dim3(8, 8, 8), 256>>>(x, pa);

    float* out = (float*)d_out;
    ScalArgs sa;
    sa.w2[0] = (const float*)d_in[3];  sa.b2[0] = (const float*)d_in[4];
    sa.w2[1] = (const float*)d_in[7];  sa.b2[1] = (const float*)d_in[8];
    sa.w2[2] = (const float*)d_in[11]; sa.b2[2] = (const float*)d_in[12];
    pair_scalar_kernel<<<dim3(8, 8, 3), 256>>>(sa, out);

    lab_kernel<<<dim3(16, 4, 8), 256>>>((const float*)d_in[15], (const float*)d_in[16],
                                        out + 3 * OUT_HEAD);

    sym_kernel<<<512, 256>>>(out);
}

// round 3
// speedup vs baseline: 1.0860x; 1.0031x over previous
#include <cuda_runtime.h>

#define NB 8
#define NS 128
#define ND 512
#define NL 512
#define NR 50
#define NBS 1024            // NB*NS
#define OUT_HEAD (NB*NS*NS) // 131072

// Projection scratch: [head*2+side][row=b*S+i][l]. side0 = left, side1 = right (+b1 folded).
__device__ float g_P[8][NBS][NL];

struct ProjArgs { const float* W1[4]; const float* b1[4]; };
struct ScalArgs { const float* w2[3]; const float* b2[3]; };

typedef unsigned long long ULL;
union U64 { ULL u; float2 f; };

__device__ __forceinline__ float tanha(float x) {
    float y; asm("tanh.approx.f32 %0, %1;" : "=f"(y) : "f"(x)); return y;
}
__device__ __forceinline__ void ffma2(ULL& d, ULL a, ULL b) {
    asm("fma.rn.f32x2 %0, %1, %2, %0;" : "+l"(d) : "l"(a), "l"(b));
}
__device__ __forceinline__ ULL pack2(float lo, float hi) {
    ULL u;
    asm("mov.b64 %0, {%1, %2};" : "=l"(u) : "r"(__float_as_uint(lo)), "r"(__float_as_uint(hi)));
    return u;
}

// ---------------------------------------------------------------------------
// Kernel A: projections.  C[z] = X(1024x512) @ W1[head][side] (512x512), +b1 on side 1.
// Tile 128x64, k-chunk 32, 256 threads, 8x4 micro-tile, packed f32x2 FMA.
// ---------------------------------------------------------------------------
__global__ __launch_bounds__(256) void proj_kernel(const float* __restrict__ x, ProjArgs pa) {
    const int z = blockIdx.z, head = z >> 1, side = z & 1;
    const float* __restrict__ W = pa.W1[head] + (side ? ND * NL : 0);
    const int r0 = blockIdx.x * 128, c0 = blockIdx.y * 64;
    __shared__ float Xs[128][33];
    __shared__ float Ws[32][64];
    const int t = threadIdx.x, tx = t & 15, ty = t >> 4;
    ULL acc2[8][2];
#pragma unroll
    for (int r = 0; r < 8; r++) { acc2[r][0] = 0ull; acc2[r][1] = 0ull; }

    for (int k0 = 0; k0 < ND; k0 += 32) {
#pragma unroll
        for (int m = 0; m < 4; m++) {
            int e = t + 256 * m, row = e >> 3, c4 = (e & 7) << 2;
            float4 v = *(const float4*)(x + (r0 + row) * ND + k0 + c4);
            Xs[row][c4] = v.x; Xs[row][c4+1] = v.y; Xs[row][c4+2] = v.z; Xs[row][c4+3] = v.w;
        }
#pragma unroll
        for (int m = 0; m < 2; m++) {
            int e = t + 256 * m, kk = e >> 4, c4 = (e & 15) << 2;
            *(float4*)&Ws[kk][c4] = *(const float4*)(W + (k0 + kk) * NL + c0 + c4);
        }
        __syncthreads();
#pragma unroll
        for (int kk = 0; kk < 32; kk++) {
            float4 bv = *(const float4*)&Ws[kk][tx << 2];
            ULL b01 = pack2(bv.x, bv.y);
            ULL b23 = pack2(bv.z, bv.w);
#pragma unroll
            for (int r = 0; r < 8; r++) {
                float a = Xs[(ty << 3) + r][kk];
                ULL aa = pack2(a, a);
                ffma2(acc2[r][0], aa, b01);
                ffma2(acc2[r][1], aa, b23);
            }
        }
        __syncthreads();
    }
    float bias[4] = {0.f, 0.f, 0.f, 0.f};
    if (side) {
        const float* b1 = pa.b1[head];
#pragma unroll
        for (int c = 0; c < 4; c++) bias[c] = b1[c0 + (tx << 2) + c];
    }
    float* o = &g_P[z][0][0];
#pragma unroll
    for (int r = 0; r < 8; r++) {
        U64 u0, u1; u0.u = acc2[r][0]; u1.u = acc2[r][1];
        float4 v = make_float4(u0.f.x + bias[0], u0.f.y + bias[1],
                               u1.f.x + bias[2], u1.f.y + bias[3]);
        *(float4*)&o[(r0 + (ty << 3) + r) * NL + c0 + (tx << 2)] = v;
    }
}

// ---------------------------------------------------------------------------
// Kernel B: the three n_out=1 heads.  out[b,i,j] = sum_l tanh(L[i,l]+R[j,l])*w2[l] + b2.
// Block = (head, b, 64i x 32j tile), 256 threads, 4x2 micro (8 tanh per lk per thread).
// Span (head 0) skips tiles strictly above the diagonal (filled later by sym_kernel).
// ---------------------------------------------------------------------------
__global__ __launch_bounds__(256) void pair_scalar_kernel(ScalArgs sa, float* __restrict__ out) {
    const int head = blockIdx.z, b = blockIdx.y;
    const int it = blockIdx.x >> 2, jt = blockIdx.x & 3;
    if (head == 0 && it * 64 + 63 < jt * 32) return;   // strictly upper: mirrored later
    const int i0 = it * 64, j0 = jt * 32;
    __shared__ float Ls[32][68];   // [lk][i], 272B rows (16B aligned), 4-way STS conflict ok
    __shared__ float Rs[32][36];   // [lk][j]
    __shared__ float w2s[32];
    const float* __restrict__ Lg = &g_P[head * 2][b * NS + i0][0];
    const float* __restrict__ Rg = &g_P[head * 2 + 1][b * NS + j0][0];
    const float* __restrict__ w2 = sa.w2[head];
    const int t = threadIdx.x;
    const int ti4 = (t >> 4) << 2;     // 16 i-groups of 4
    const int tj2 = (t & 15) << 1;     // 16 j-groups of 2
    float acc[4][2];
#pragma unroll
    for (int r = 0; r < 4; r++) { acc[r][0] = 0.f; acc[r][1] = 0.f; }

    for (int l0 = 0; l0 < NL; l0 += 32) {
#pragma unroll
        for (int m = 0; m < 8; m++) {        // 64 rows x 32 lk
            int e = t + 256 * m, lk = e & 31, i = e >> 5;
            Ls[lk][i] = Lg[i * NL + l0 + lk];
        }
#pragma unroll
        for (int m = 0; m < 4; m++) {        // 32 rows x 32 lk
            int e = t + 256 * m, lk = e & 31, j = e >> 5;
            Rs[lk][j] = Rg[j * NL + l0 + lk];
        }
        if (t < 32) w2s[t] = w2[l0 + t];
        __syncthreads();
#pragma unroll
        for (int lk = 0; lk < 32; lk++) {
            float4 xv = *(const float4*)&Ls[lk][ti4];
            float2 yv = *(const float2*)&Rs[lk][tj2];
            float w = w2s[lk];
            float xs[4] = {xv.x, xv.y, xv.z, xv.w};
#pragma unroll
            for (int r = 0; r < 4; r++) {
                acc[r][0] = fmaf(tanha(xs[r] + yv.x), w, acc[r][0]);
                acc[r][1] = fmaf(tanha(xs[r] + yv.y), w, acc[r][1]);
            }
        }
        __syncthreads();
    }
    const float b2 = sa.b2[head][0];
    float* o = out + head * OUT_HEAD + b * NS * NS;
#pragma unroll
    for (int r = 0; r < 4; r++) {
        o[(i0 + ti4 + r) * NS + j0 + tj2]     = acc[r][0] + b2;
        o[(i0 + ti4 + r) * NS + j0 + tj2 + 1] = acc[r][1] + b2;
    }
}

// ---------------------------------------------------------------------------
// Kernel C: lab head (R=50).  Block = (b, 32i x 8j = 256 pairs).
// Per 16-l chunk: build H tile (tanh) in smem, then 256x56 += H(256x16)@W2dup(16x56)
// with packed fma.rn.f32x2. Thread owns 8 pairs (1 i-row, all 8 j) x 7 outputs.
// ---------------------------------------------------------------------------
#define LCH 16
__global__ __launch_bounds__(256) void lab_kernel(const float* __restrict__ W2,
                                                  const float* __restrict__ b2,
                                                  float* __restrict__ out) {
    const int b = blockIdx.z, it = blockIdx.y, jt = blockIdx.x;
    const int i0 = it * 32, j0 = jt * 8;
    __shared__ float Ls[32][LCH + 1];          // [i][lk]
    __shared__ float Rs[8][LCH + 1];           // [j][lk]
    __shared__ float Hs[LCH][264];             // [lk][pair]; pair = i*8+j
    __shared__ ULL   W2d[LCH][57];             // duplicated (w,w) pairs, zero-padded o>=50
    const float* __restrict__ Lg = &g_P[6][b * NS + i0][0];
    const float* __restrict__ Rg = &g_P[7][b * NS + j0][0];
    const int t = threadIdx.x, og = t & 7, pgrp = t >> 3;  // og: 7 outs; pgrp: i-row, 8 pairs

    ULL acc2[4][7];
#pragma unroll
    for (int q = 0; q < 4; q++)
#pragma unroll
        for (int c = 0; c < 7; c++) acc2[q][c] = 0ull;

    for (int l0 = 0; l0 < NL; l0 += LCH) {
#pragma unroll
        for (int m = 0; m < 2; m++) {          // 32 i x 16 lk = 512
            int e = t + 256 * m, i = e >> 4, lk = e & 15;
            Ls[i][lk] = Lg[i * NL + l0 + lk];
        }
        if (t < 128) { int j = t >> 4, lk = t & 15; Rs[j][lk] = Rg[j * NL + l0 + lk]; }
#pragma unroll
        for (int m = 0; m < 4; m++) {          // 16 lk x 56 outs = 896
            int e = t + 256 * m;
            if (e < LCH * 56) {
                int lk = e / 56, oo = e - lk * 56;
                float w = (oo < NR) ? W2[(l0 + lk) * NR + oo] : 0.f;
                W2d[lk][oo] = pack2(w, w);
            }
        }
        __syncthreads();
        // H tile: 16 lk x 256 pairs
#pragma unroll
        for (int m = 0; m < LCH; m++) {
            int e = t + 256 * m, lk = e >> 8, p = e & 255;
            Hs[lk][p] = tanha(Ls[p >> 3][lk] + Rs[p & 7][lk]);
        }
        __syncthreads();
        // GEMM with packed f32x2
#pragma unroll
        for (int lk = 0; lk < LCH; lk++) {
            ULL h[4];
#pragma unroll
            for (int q = 0; q < 4; q++)
                h[q] = *(const ULL*)&Hs[lk][pgrp * 8 + q * 2];
#pragma unroll
            for (int c = 0; c < 7; c++) {
                ULL w = W2d[lk][og * 7 + c];
#pragma unroll
                for (int q = 0; q < 4; q++) ffma2(acc2[q][c], h[q], w);
            }
        }
        __syncthreads();
    }
    // epilogue: thread's pairs are (i = i0+pgrp, j = j0 + 2q+k)
#pragma unroll
    for (int c = 0; c < 7; c++) {
        int o = og * 7 + c;
        if (o < NR) {
            float bv = b2[o];
            float* obase = out + ((b * NS + i0 + pgrp) * NS + j0) * NR + o;
#pragma unroll
            for (int q = 0; q < 4; q++) {
                U64 u; u.u = acc2[q][c];
                obase[(2 * q) * NR]     = u.f.x + bv;
                obase[(2 * q + 1) * NR] = u.f.y + bv;
            }
        }
    }
}

// ---------------------------------------------------------------------------
// Kernel D: span symmetrization. final[b,i,j] = raw[b,max(i,j),min(i,j)]:
// copy lower triangle over upper.
// ---------------------------------------------------------------------------
__global__ void sym_kernel(float* __restrict__ out) {
    int idx = blockIdx.x * 256 + threadIdx.x;
    int b = idx >> 14, r = idx & 16383, i = r >> 7, j = r & 127;
    if (i < j) out[idx] = out[(b << 14) + (j << 7) + i];
}

// ---------------------------------------------------------------------------
extern "C" void kernel_launch(void* const* d_in, const int* in_sizes, int n_in,
                              void* d_out, int out_size) {
    (void)in_sizes; (void)n_in; (void)out_size;
    const float* x = (const float*)d_in[0];

    ProjArgs pa;
    pa.W1[0] = (const float*)d_in[1];  pa.b1[0] = (const float*)d_in[2];
    pa.W1[1] = (const float*)d_in[5];  pa.b1[1] = (const float*)d_in[6];
    pa.W1[2] = (const float*)d_in[9];  pa.b1[2] = (const float*)d_in[10];
    pa.W1[3] = (const float*)d_in[13]; pa.b1[3] = (const float*)d_in[14];
    proj_kernel<<<dim3(8, 8, 8), 256>>>(x, pa);

    float* out = (float*)d_out;
    ScalArgs sa;
    sa.w2[0] = (const float*)d_in[3];  sa.b2[0] = (const float*)d_in[4];
    sa.w2[1] = (const float*)d_in[7];  sa.b2[1] = (const float*)d_in[8];
    sa.w2[2] = (const float*)d_in[11]; sa.b2[2] = (const float*)d_in[12];
    pair_scalar_kernel<<<dim3(8, 8, 3), 256>>>(sa, out);

    lab_kernel<<<dim3(16, 4, 8), 256>>>((const float*)d_in[15], (const float*)d_in[16],
                                        out + 3 * OUT_HEAD);

    sym_kernel<<<512, 256>>>(out);
}

// round 7
// speedup vs baseline: 1.7435x; 1.6055x over previous
#include <cuda_runtime.h>
#include <cuda_bf16.h>
#include <stdint.h>

#define NB 8
#define NS 128
#define ND 512
#define NL 512
#define NR 50
#define NBS 1024
#define OUT_HEAD (NB*NS*NS)

__device__ __align__(1024) float g_P[8][NBS][NL];
__device__ __align__(1024) __nv_bfloat16 g_Xhi[NBS][ND];
__device__ __align__(1024) __nv_bfloat16 g_Xlo[NBS][ND];
__device__ __align__(1024) __nv_bfloat16 g_Wthi[8][NL][ND];   // [z][n][k]
__device__ __align__(1024) __nv_bfloat16 g_Wtlo[8][NL][ND];
__device__ __align__(1024) __nv_bfloat16 g_W2thi[64][NL];     // [o][l], o padded to 64
__device__ __align__(1024) __nv_bfloat16 g_W2tlo[64][NL];

struct ProjArgs { const float* W1[4]; const float* b1[4]; };
struct ScalArgs { const float* w2[3]; const float* b2[3]; };

__device__ __forceinline__ float tanha(float x) {
    float y; asm("tanh.approx.f32 %0, %1;" : "=f"(y) : "f"(x)); return y;
}
__device__ __forceinline__ uint32_t s2u(const void* p) {
    uint32_t a;
    asm("{ .reg .u64 t; cvta.to.shared.u64 t, %1; cvt.u32.u64 %0, t; }" : "=r"(a) : "l"(p));
    return a;
}
__device__ __forceinline__ void ldm4(uint32_t* r, uint32_t a) {
    asm volatile("ldmatrix.sync.aligned.m8n8.x4.shared.b16 {%0,%1,%2,%3}, [%4];"
        : "=r"(r[0]), "=r"(r[1]), "=r"(r[2]), "=r"(r[3]) : "r"(a));
}
__device__ __forceinline__ void mma_bb(float* c, const uint32_t* a, const uint32_t* b) {
    asm volatile("mma.sync.aligned.m16n8k16.row.col.f32.bf16.bf16.f32 "
        "{%0,%1,%2,%3}, {%4,%5,%6,%7}, {%8,%9}, {%0,%1,%2,%3};"
        : "+f"(c[0]), "+f"(c[1]), "+f"(c[2]), "+f"(c[3])
        : "r"(a[0]), "r"(a[1]), "r"(a[2]), "r"(a[3]), "r"(b[0]), "r"(b[1]));
}
__device__ __forceinline__ void cpa16(uint32_t s, const void* g) {
    asm volatile("cp.async.ca.shared.global [%0], [%1], 16;" :: "r"(s), "l"(g));
}
__device__ __forceinline__ void cpwait() {
    asm volatile("cp.async.commit_group;\n\tcp.async.wait_group 0;" ::: "memory");
}
__device__ __forceinline__ uint32_t pack_bf2(float a, float b) {
    return ((uint32_t)__bfloat16_as_ushort(__float2bfloat16(b)) << 16)
         | (uint32_t)__bfloat16_as_ushort(__float2bfloat16(a));
}

// ---------------- prep: fp32 -> split bf16 ----------------
__global__ void prep_x(const float* __restrict__ x) {
    int i = blockIdx.x * 256 + threadIdx.x;
    float v = x[i];
    __nv_bfloat16 h = __float2bfloat16(v);
    (&g_Xhi[0][0])[i] = h;
    (&g_Xlo[0][0])[i] = __float2bfloat16(v - __bfloat162float(h));
}
__global__ void prep_w(ProjArgs pa) {
    __shared__ float tile[32][33];
    int z = blockIdx.z, head = z >> 1, side = z & 1;
    int k0 = blockIdx.x * 32, n0 = blockIdx.y * 32;
    const float* W = pa.W1[head] + side * ND * NL;
    int t = threadIdx.x, c = t & 31, r4 = (t >> 5) * 4;
#pragma unroll
    for (int q = 0; q < 4; q++) tile[r4 + q][c] = W[(k0 + r4 + q) * NL + n0 + c];
    __syncthreads();
#pragma unroll
    for (int q = 0; q < 4; q++) {
        float v = tile[c][r4 + q];
        __nv_bfloat16 h = __float2bfloat16(v);
        g_Wthi[z][n0 + r4 + q][k0 + c] = h;
        g_Wtlo[z][n0 + r4 + q][k0 + c] = __float2bfloat16(v - __bfloat162float(h));
    }
}
__global__ void prep_w2(const float* __restrict__ W2) {
    int e = blockIdx.x * 256 + threadIdx.x;   // 64*512
    int o = e >> 9, l = e & 511;
    float v = (o < NR) ? W2[l * NR + o] : 0.f;
    __nv_bfloat16 h = __float2bfloat16(v);
    g_W2thi[o][l] = h;
    g_W2tlo[o][l] = __float2bfloat16(v - __bfloat162float(h));
}

// ---------------- projections via mma.sync ----------------
// grid (8 Mtile, 4 Ntile, 8 z), 256 thr. CTA 128x128, warp 64x32, K chunks of 32.
#define PAD 40
__global__ __launch_bounds__(256) void proj_mma(ProjArgs pa) {
    __shared__ __nv_bfloat16 Ah[128][PAD], Al[128][PAD], Bh[128][PAD], Bl[128][PAD];
    const int t = threadIdx.x, lane = t & 31, w = t >> 5;
    const int wm = w >> 2, wn = w & 3;          // warp grid 2x4
    const int z = blockIdx.z, head = z >> 1, side = z & 1;
    const int r0 = blockIdx.x * 128, c0 = blockIdx.y * 128;
    const float* __restrict__ b1p = pa.b1[head];

    float acc[4][4][4];
#pragma unroll
    for (int mt = 0; mt < 4; mt++)
#pragma unroll
        for (int nt = 0; nt < 4; nt++) { acc[mt][nt][0]=0.f; acc[mt][nt][1]=0.f; acc[mt][nt][2]=0.f; acc[mt][nt][3]=0.f; }

    const int lrow = t >> 2, lq = (t & 3) * 8;  // loader mapping: 64 rows per 256-step
    for (int kc = 0; kc < ND; kc += 32) {
#pragma unroll
        for (int m = 0; m < 2; m++) {
            int row = lrow + 64 * m;
            cpa16(s2u(&Ah[row][lq]), &g_Xhi[r0 + row][kc + lq]);
            cpa16(s2u(&Al[row][lq]), &g_Xlo[r0 + row][kc + lq]);
            cpa16(s2u(&Bh[row][lq]), &g_Wthi[z][c0 + row][kc + lq]);
            cpa16(s2u(&Bl[row][lq]), &g_Wtlo[z][c0 + row][kc + lq]);
        }
        cpwait();
        __syncthreads();
#pragma unroll
        for (int ks = 0; ks < 2; ks++) {
            const int k0 = ks * 16;
            uint32_t ah[4][4], al[4][4], bh[4][2], bl[4][2];
#pragma unroll
            for (int mt = 0; mt < 4; mt++) {
                int ar = wm * 64 + mt * 16 + (lane & 15), ac = k0 + ((lane >> 4) << 3);
                ldm4(ah[mt], s2u(&Ah[ar][ac]));
                ldm4(al[mt], s2u(&Al[ar][ac]));
            }
#pragma unroll
            for (int nh = 0; nh < 2; nh++) {
                int br = wn * 32 + nh * 16 + ((lane >> 4) << 3) + (lane & 7);
                int bc = k0 + (((lane >> 3) & 1) << 3);
                uint32_t r[4];
                ldm4(r, s2u(&Bh[br][bc]));
                bh[nh*2][0]=r[0]; bh[nh*2][1]=r[1]; bh[nh*2+1][0]=r[2]; bh[nh*2+1][1]=r[3];
                ldm4(r, s2u(&Bl[br][bc]));
                bl[nh*2][0]=r[0]; bl[nh*2][1]=r[1]; bl[nh*2+1][0]=r[2]; bl[nh*2+1][1]=r[3];
            }
#pragma unroll
            for (int mt = 0; mt < 4; mt++)
#pragma unroll
                for (int nt = 0; nt < 4; nt++) {
                    mma_bb(acc[mt][nt], ah[mt], bh[nt]);
                    mma_bb(acc[mt][nt], ah[mt], bl[nt]);
                    mma_bb(acc[mt][nt], al[mt], bh[nt]);
                }
        }
        __syncthreads();
    }
#pragma unroll
    for (int mt = 0; mt < 4; mt++)
#pragma unroll
        for (int nt = 0; nt < 4; nt++) {
            int row = r0 + wm * 64 + mt * 16 + (lane >> 2);
            int col = c0 + wn * 32 + nt * 8 + ((lane & 3) << 1);
            float bb0 = 0.f, bb1 = 0.f;
            if (side) { bb0 = __ldg(&b1p[col]); bb1 = __ldg(&b1p[col + 1]); }
            float2 v0 = make_float2(acc[mt][nt][0] + bb0, acc[mt][nt][1] + bb1);
            float2 v1 = make_float2(acc[mt][nt][2] + bb0, acc[mt][nt][3] + bb1);
            *(float2*)&g_P[z][row][col] = v0;
            *(float2*)&g_P[z][row + 8][col] = v1;
        }
}

// ---------------- lab head: fused tanh + mma.sync ----------------
// grid (16 jt, 8 it, 8 b). M=128 pairs (16i x 8j), N=64 (padded), K=512, chunks of 32.
__global__ __launch_bounds__(256) void lab_mma(const float* __restrict__ b2,
                                               float* __restrict__ out) {
    __shared__ float Lc[16][36], Rc[8][36];
    __shared__ __nv_bfloat16 Hh[128][PAD], Hl[128][PAD], W2h[64][PAD], W2l[64][PAD];
    const int t = threadIdx.x, lane = t & 31, w = t >> 5;
    const int wm = w >> 2, wn = w & 3;          // warp grid 2x4, warp tile 64x16
    const int b = blockIdx.z, i0 = blockIdx.y * 16, j0 = blockIdx.x * 8;

    float acc[4][2][4];
#pragma unroll
    for (int mt = 0; mt < 4; mt++)
#pragma unroll
        for (int nt = 0; nt < 2; nt++) { acc[mt][nt][0]=0.f; acc[mt][nt][1]=0.f; acc[mt][nt][2]=0.f; acc[mt][nt][3]=0.f; }

    const int p = t >> 1, kh = t & 1;           // tanh producer: pair, k-half
    for (int kc = 0; kc < NL; kc += 32) {
        if (t < 128) {
            int row = t >> 3, q = t & 7;
            cpa16(s2u(&Lc[row][q * 4]), &g_P[6][b * NS + i0 + row][kc + q * 4]);
        } else if (t < 192) {
            int tt = t - 128, row = tt >> 3, q = tt & 7;
            cpa16(s2u(&Rc[row][q * 4]), &g_P[7][b * NS + j0 + row][kc + q * 4]);
        }
        { int row = t >> 2, q = (t & 3) * 8;
          cpa16(s2u(&W2h[row][q]), &g_W2thi[row][kc + q]);
          cpa16(s2u(&W2l[row][q]), &g_W2tlo[row][kc + q]); }
        cpwait();
        __syncthreads();
        // tanh + split -> H tiles
        {
            const float* Lr = &Lc[p >> 3][kh * 16];
            const float* Rr = &Rc[p & 7][kh * 16];
            uint32_t hv[8], lv[8];
#pragma unroll
            for (int q = 0; q < 4; q++) {
                float4 lx = *(const float4*)&Lr[q * 4];
                float4 rx = *(const float4*)&Rr[q * 4];
                float h0 = tanha(lx.x + rx.x), h1 = tanha(lx.y + rx.y);
                float h2 = tanha(lx.z + rx.z), h3 = tanha(lx.w + rx.w);
                float g0 = __bfloat162float(__float2bfloat16(h0));
                float g1 = __bfloat162float(__float2bfloat16(h1));
                float g2 = __bfloat162float(__float2bfloat16(h2));
                float g3 = __bfloat162float(__float2bfloat16(h3));
                hv[q*2]   = pack_bf2(h0, h1);
                hv[q*2+1] = pack_bf2(h2, h3);
                lv[q*2]   = pack_bf2(h0 - g0, h1 - g1);
                lv[q*2+1] = pack_bf2(h2 - g2, h3 - g3);
            }
            *(uint4*)&Hh[p][kh * 16]     = make_uint4(hv[0], hv[1], hv[2], hv[3]);
            *(uint4*)&Hh[p][kh * 16 + 8] = make_uint4(hv[4], hv[5], hv[6], hv[7]);
            *(uint4*)&Hl[p][kh * 16]     = make_uint4(lv[0], lv[1], lv[2], lv[3]);
            *(uint4*)&Hl[p][kh * 16 + 8] = make_uint4(lv[4], lv[5], lv[6], lv[7]);
        }
        __syncthreads();
#pragma unroll
        for (int ks = 0; ks < 2; ks++) {
            const int k0 = ks * 16;
            uint32_t ah[4][4], al[4][4], bh[2][2], bl[2][2];
#pragma unroll
            for (int mt = 0; mt < 4; mt++) {
                int ar = wm * 64 + mt * 16 + (lane & 15), ac = k0 + ((lane >> 4) << 3);
                ldm4(ah[mt], s2u(&Hh[ar][ac]));
                ldm4(al[mt], s2u(&Hl[ar][ac]));
            }
            {
                int br = wn * 16 + ((lane >> 4) << 3) + (lane & 7);
                int bc = k0 + (((lane >> 3) & 1) << 3);
                uint32_t r[4];
                ldm4(r, s2u(&W2h[br][bc]));
                bh[0][0]=r[0]; bh[0][1]=r[1]; bh[1][0]=r[2]; bh[1][1]=r[3];
                ldm4(r, s2u(&W2l[br][bc]));
                bl[0][0]=r[0]; bl[0][1]=r[1]; bl[1][0]=r[2]; bl[1][1]=r[3];
            }
#pragma unroll
            for (int mt = 0; mt < 4; mt++)
#pragma unroll
                for (int nt = 0; nt < 2; nt++) {
                    mma_bb(acc[mt][nt], ah[mt], bh[nt]);
                    mma_bb(acc[mt][nt], ah[mt], bl[nt]);
                    mma_bb(acc[mt][nt], al[mt], bh[nt]);
                }
        }
        __syncthreads();
    }
#pragma unroll
    for (int mt = 0; mt < 4; mt++)
#pragma unroll
        for (int nt = 0; nt < 2; nt++) {
            int o = wn * 16 + nt * 8 + ((lane & 3) << 1);
            if (o < NR) {
                float bb0 = __ldg(&b2[o]), bb1 = __ldg(&b2[o + 1]);
#pragma unroll
                for (int half = 0; half < 2; half++) {
                    int pp = wm * 64 + mt * 16 + (lane >> 2) + half * 8;
                    int i = i0 + (pp >> 3), j = j0 + (pp & 7);
                    float2 v = make_float2(acc[mt][nt][half*2] + bb0,
                                           acc[mt][nt][half*2+1] + bb1);
                    *(float2*)&out[((b * NS + i) * NS + j) * NR + o] = v;
                }
            }
        }
}

// ---------------- scalar pair heads ----------------
__global__ __launch_bounds__(256) void pair_scalar_kernel(ScalArgs sa, float* __restrict__ out) {
    const int head = blockIdx.z, b = blockIdx.y;
    const int it = blockIdx.x >> 2, jt = blockIdx.x & 3;
    if (head == 0 && it * 64 + 63 < jt * 32) return;
    const int i0 = it * 64, j0 = jt * 32;
    __shared__ float Ls[32][68];
    __shared__ float Rs[32][36];
    __shared__ float w2s[32];
    const float* __restrict__ Lg = &g_P[head * 2][b * NS + i0][0];
    const float* __restrict__ Rg = &g_P[head * 2 + 1][b * NS + j0][0];
    const float* __restrict__ w2 = sa.w2[head];
    const int t = threadIdx.x;
    const int ti4 = (t >> 4) << 2, tj2 = (t & 15) << 1;
    float acc[4][2];
#pragma unroll
    for (int r = 0; r < 4; r++) { acc[r][0] = 0.f; acc[r][1] = 0.f; }
    for (int l0 = 0; l0 < NL; l0 += 32) {
#pragma unroll
        for (int m = 0; m < 8; m++) {
            int e = t + 256 * m, lk = e & 31, i = e >> 5;
            Ls[lk][i] = Lg[i * NL + l0 + lk];
        }
#pragma unroll
        for (int m = 0; m < 4; m++) {
            int e = t + 256 * m, lk = e & 31, j = e >> 5;
            Rs[lk][j] = Rg[j * NL + l0 + lk];
        }
        if (t < 32) w2s[t] = w2[l0 + t];
        __syncthreads();
#pragma unroll
        for (int lk = 0; lk < 32; lk++) {
            float4 xv = *(const float4*)&Ls[lk][ti4];
            float2 yv = *(const float2*)&Rs[lk][tj2];
            float wv = w2s[lk];
            float xs[4] = {xv.x, xv.y, xv.z, xv.w};
#pragma unroll
            for (int r = 0; r < 4; r++) {
                acc[r][0] = fmaf(tanha(xs[r] + yv.x), wv, acc[r][0]);
                acc[r][1] = fmaf(tanha(xs[r] + yv.y), wv, acc[r][1]);
            }
        }
        __syncthreads();
    }
    const float bb = sa.b2[head][0];
    float* o = out + head * OUT_HEAD + b * NS * NS;
#pragma unroll
    for (int r = 0; r < 4; r++) {
        o[(i0 + ti4 + r) * NS + j0 + tj2]     = acc[r][0] + bb;
        o[(i0 + ti4 + r) * NS + j0 + tj2 + 1] = acc[r][1] + bb;
    }
}

__global__ void sym_kernel(float* __restrict__ out) {
    int idx = blockIdx.x * 256 + threadIdx.x;
    int b = idx >> 14, r = idx & 16383, i = r >> 7, j = r & 127;
    if (i < j) out[idx] = out[(b << 14) + (j << 7) + i];
}

// ---------------------------------------------------------------------------
extern "C" void kernel_launch(void* const* d_in, const int* in_sizes, int n_in,
                              void* d_out, int out_size) {
    (void)in_sizes; (void)n_in; (void)out_size;
    const float* x = (const float*)d_in[0];
    ProjArgs pa;
    pa.W1[0] = (const float*)d_in[1];  pa.b1[0] = (const float*)d_in[2];
    pa.W1[1] = (const float*)d_in[5];  pa.b1[1] = (const float*)d_in[6];
    pa.W1[2] = (const float*)d_in[9];  pa.b1[2] = (const float*)d_in[10];
    pa.W1[3] = (const float*)d_in[13]; pa.b1[3] = (const float*)d_in[14];
    ScalArgs sa;
    sa.w2[0] = (const float*)d_in[3];  sa.b2[0] = (const float*)d_in[4];
    sa.w2[1] = (const float*)d_in[7];  sa.b2[1] = (const float*)d_in[8];
    sa.w2[2] = (const float*)d_in[11]; sa.b2[2] = (const float*)d_in[12];
    float* out = (float*)d_out;

    prep_x<<<2048, 256>>>(x);
    prep_w<<<dim3(16, 16, 8), 256>>>(pa);
    prep_w2<<<128, 256>>>((const float*)d_in[15]);

    proj_mma<<<dim3(8, 4, 8), 256>>>(pa);

    pair_scalar_kernel<<<dim3(8, 8, 3), 256>>>(sa, out);

    lab_mma<<<dim3(16, 8, 8), 256>>>((const float*)d_in[16], out + 3 * OUT_HEAD);

    sym_kernel<<<512, 256>>>(out);
}

// round 8
// speedup vs baseline: 1.8749x; 1.0754x over previous
#include <cuda_runtime.h>
#include <cuda_bf16.h>
#include <stdint.h>

#define NB 8
#define NS 128
#define ND 512
#define NL 512
#define NR 50
#define NBS 1024
#define OUT_HEAD (NB*NS*NS)

__device__ __align__(1024) float g_P[8][NBS][NL];
__device__ __align__(1024) __nv_bfloat16 g_Xhi[NBS][ND];
__device__ __align__(1024) __nv_bfloat16 g_Xlo[NBS][ND];
__device__ __align__(1024) __nv_bfloat16 g_Wthi[8][NL][ND];   // [z][n][k]
__device__ __align__(1024) __nv_bfloat16 g_Wtlo[8][NL][ND];
__device__ __align__(1024) __nv_bfloat16 g_W2thi[64][NL];     // [o][l], o padded to 64
__device__ __align__(1024) __nv_bfloat16 g_W2tlo[64][NL];

struct ProjArgs { const float* W1[4]; const float* b1[4]; };
struct ScalArgs { const float* w2[3]; const float* b2[3]; };

__device__ __forceinline__ float tanha(float x) {
    float y; asm("tanh.approx.f32 %0, %1;" : "=f"(y) : "f"(x)); return y;
}
__device__ __forceinline__ uint32_t s2u(const void* p) {
    uint32_t a;
    asm("{ .reg .u64 t; cvta.to.shared.u64 t, %1; cvt.u32.u64 %0, t; }" : "=r"(a) : "l"(p));
    return a;
}
__device__ __forceinline__ void ldm4(uint32_t* r, uint32_t a) {
    asm volatile("ldmatrix.sync.aligned.m8n8.x4.shared.b16 {%0,%1,%2,%3}, [%4];"
        : "=r"(r[0]), "=r"(r[1]), "=r"(r[2]), "=r"(r[3]) : "r"(a));
}
__device__ __forceinline__ void mma_bb(float* c, const uint32_t* a, const uint32_t* b) {
    asm volatile("mma.sync.aligned.m16n8k16.row.col.f32.bf16.bf16.f32 "
        "{%0,%1,%2,%3}, {%4,%5,%6,%7}, {%8,%9}, {%0,%1,%2,%3};"
        : "+f"(c[0]), "+f"(c[1]), "+f"(c[2]), "+f"(c[3])
        : "r"(a[0]), "r"(a[1]), "r"(a[2]), "r"(a[3]), "r"(b[0]), "r"(b[1]));
}
__device__ __forceinline__ void cpa16(uint32_t s, const void* g) {
    asm volatile("cp.async.ca.shared.global [%0], [%1], 16;" :: "r"(s), "l"(g));
}
__device__ __forceinline__ void cpcommit() {
    asm volatile("cp.async.commit_group;" ::: "memory");
}
__device__ __forceinline__ void cpwait1() {
    asm volatile("cp.async.wait_group 1;" ::: "memory");
}
__device__ __forceinline__ void cpwait0() {
    asm volatile("cp.async.wait_group 0;" ::: "memory");
}
__device__ __forceinline__ uint32_t pack_bf2(float a, float b) {
    return ((uint32_t)__bfloat16_as_ushort(__float2bfloat16(b)) << 16)
         | (uint32_t)__bfloat16_as_ushort(__float2bfloat16(a));
}

// ---------------- prep: fp32 -> split bf16 ----------------
__global__ void prep_x(const float* __restrict__ x) {
    int i = blockIdx.x * 256 + threadIdx.x;
    float v = x[i];
    __nv_bfloat16 h = __float2bfloat16(v);
    (&g_Xhi[0][0])[i] = h;
    (&g_Xlo[0][0])[i] = __float2bfloat16(v - __bfloat162float(h));
}
__global__ void prep_w(ProjArgs pa) {
    __shared__ float tile[32][33];
    int z = blockIdx.z, head = z >> 1, side = z & 1;
    int k0 = blockIdx.x * 32, n0 = blockIdx.y * 32;
    const float* W = pa.W1[head] + side * ND * NL;
    int t = threadIdx.x, c = t & 31, r4 = (t >> 5) * 4;
#pragma unroll
    for (int q = 0; q < 4; q++) tile[r4 + q][c] = W[(k0 + r4 + q) * NL + n0 + c];
    __syncthreads();
#pragma unroll
    for (int q = 0; q < 4; q++) {
        float v = tile[c][r4 + q];
        __nv_bfloat16 h = __float2bfloat16(v);
        g_Wthi[z][n0 + r4 + q][k0 + c] = h;
        g_Wtlo[z][n0 + r4 + q][k0 + c] = __float2bfloat16(v - __bfloat162float(h));
    }
}
__global__ void prep_w2(const float* __restrict__ W2) {
    int e = blockIdx.x * 256 + threadIdx.x;   // 64*512
    int o = e >> 9, l = e & 511;
    float v = (o < NR) ? W2[l * NR + o] : 0.f;
    __nv_bfloat16 h = __float2bfloat16(v);
    g_W2thi[o][l] = h;
    g_W2tlo[o][l] = __float2bfloat16(v - __bfloat162float(h));
}

// ---------------- projections via mma.sync, 2-stage pipeline ----------------
// grid (8 Mtile, 4 Ntile, 8 z), 256 thr. CTA 128x128, warp 64x32, K chunks of 32.
#define PAD 40
#define PJ_STAGE 20480   // bf16 elements per stage (4 tiles of 128*PAD)
__global__ __launch_bounds__(256) void proj_mma(ProjArgs pa) {
    extern __shared__ __nv_bfloat16 dsm[];
    const int t = threadIdx.x, lane = t & 31, w = t >> 5;
    const int wm = w >> 2, wn = w & 3;          // warp grid 2x4
    const int z = blockIdx.z, head = z >> 1, side = z & 1;
    const int r0 = blockIdx.x * 128, c0 = blockIdx.y * 128;
    const float* __restrict__ b1p = pa.b1[head];

    float acc[4][4][4];
#pragma unroll
    for (int mt = 0; mt < 4; mt++)
#pragma unroll
        for (int nt = 0; nt < 4; nt++) { acc[mt][nt][0]=0.f; acc[mt][nt][1]=0.f; acc[mt][nt][2]=0.f; acc[mt][nt][3]=0.f; }

    const int lrow = t >> 2, lq = (t & 3) * 8;

    auto load_chunk = [&](int kc, int st) {
        __nv_bfloat16* Ah = dsm + st * PJ_STAGE;
        __nv_bfloat16* Al = Ah + 5120;
        __nv_bfloat16* Bh = Ah + 10240;
        __nv_bfloat16* Bl = Ah + 15360;
#pragma unroll
        for (int m = 0; m < 2; m++) {
            int row = lrow + 64 * m;
            cpa16(s2u(Ah + row * PAD + lq), &g_Xhi[r0 + row][kc + lq]);
            cpa16(s2u(Al + row * PAD + lq), &g_Xlo[r0 + row][kc + lq]);
            cpa16(s2u(Bh + row * PAD + lq), &g_Wthi[z][c0 + row][kc + lq]);
            cpa16(s2u(Bl + row * PAD + lq), &g_Wtlo[z][c0 + row][kc + lq]);
        }
        cpcommit();
    };

    load_chunk(0, 0);
    const int NCH = ND / 32;
    for (int c = 0; c < NCH; c++) {
        if (c + 1 < NCH) { load_chunk((c + 1) * 32, (c + 1) & 1); cpwait1(); }
        else cpwait0();
        __syncthreads();
        const __nv_bfloat16* Ah = dsm + (c & 1) * PJ_STAGE;
        const __nv_bfloat16* Al = Ah + 5120;
        const __nv_bfloat16* Bh = Ah + 10240;
        const __nv_bfloat16* Bl = Ah + 15360;
#pragma unroll
        for (int ks = 0; ks < 2; ks++) {
            const int k0 = ks * 16;
            uint32_t ah[4][4], al[4][4], bh[4][2], bl[4][2];
#pragma unroll
            for (int mt = 0; mt < 4; mt++) {
                int ar = wm * 64 + mt * 16 + (lane & 15), ac = k0 + ((lane >> 4) << 3);
                ldm4(ah[mt], s2u(Ah + ar * PAD + ac));
                ldm4(al[mt], s2u(Al + ar * PAD + ac));
            }
#pragma unroll
            for (int nh = 0; nh < 2; nh++) {
                int br = wn * 32 + nh * 16 + ((lane >> 4) << 3) + (lane & 7);
                int bc = k0 + (((lane >> 3) & 1) << 3);
                uint32_t r[4];
                ldm4(r, s2u(Bh + br * PAD + bc));
                bh[nh*2][0]=r[0]; bh[nh*2][1]=r[1]; bh[nh*2+1][0]=r[2]; bh[nh*2+1][1]=r[3];
                ldm4(r, s2u(Bl + br * PAD + bc));
                bl[nh*2][0]=r[0]; bl[nh*2][1]=r[1]; bl[nh*2+1][0]=r[2]; bl[nh*2+1][1]=r[3];
            }
#pragma unroll
            for (int mt = 0; mt < 4; mt++)
#pragma unroll
                for (int nt = 0; nt < 4; nt++) {
                    mma_bb(acc[mt][nt], ah[mt], bh[nt]);
                    mma_bb(acc[mt][nt], ah[mt], bl[nt]);
                    mma_bb(acc[mt][nt], al[mt], bh[nt]);
                }
        }
        __syncthreads();
    }
#pragma unroll
    for (int mt = 0; mt < 4; mt++)
#pragma unroll
        for (int nt = 0; nt < 4; nt++) {
            int row = r0 + wm * 64 + mt * 16 + (lane >> 2);
            int col = c0 + wn * 32 + nt * 8 + ((lane & 3) << 1);
            float bb0 = 0.f, bb1 = 0.f;
            if (side) { bb0 = __ldg(&b1p[col]); bb1 = __ldg(&b1p[col + 1]); }
            float2 v0 = make_float2(acc[mt][nt][0] + bb0, acc[mt][nt][1] + bb1);
            float2 v1 = make_float2(acc[mt][nt][2] + bb0, acc[mt][nt][3] + bb1);
            *(float2*)&g_P[z][row][col] = v0;
            *(float2*)&g_P[z][row + 8][col] = v1;
        }
}

// ---------------- lab head: fused tanh + mma.sync, 2-stage pipeline ----------------
// grid (16 jt, 8 it, 8 b). M=128 pairs (16i x 8j), N=64 (padded), K=512, chunks of 32.
__global__ __launch_bounds__(256) void lab_mma(const float* __restrict__ b2,
                                               float* __restrict__ out) {
    __shared__ float Lc[2][16][36], Rc[2][8][36];
    __shared__ __nv_bfloat16 W2h[2][64][PAD], W2l[2][64][PAD];
    __shared__ __nv_bfloat16 Hh[128][PAD], Hl[128][PAD];
    const int t = threadIdx.x, lane = t & 31, w = t >> 5;
    const int wm = w >> 2, wn = w & 3;          // warp grid 2x4, warp tile 64x16
    const int b = blockIdx.z, i0 = blockIdx.y * 16, j0 = blockIdx.x * 8;

    float acc[4][2][4];
#pragma unroll
    for (int mt = 0; mt < 4; mt++)
#pragma unroll
        for (int nt = 0; nt < 2; nt++) { acc[mt][nt][0]=0.f; acc[mt][nt][1]=0.f; acc[mt][nt][2]=0.f; acc[mt][nt][3]=0.f; }

    const int p = t >> 1, kh = t & 1;           // tanh producer: pair, k-half

    auto load_chunk = [&](int kc, int st) {
        if (t < 128) {
            int row = t >> 3, q = t & 7;
            cpa16(s2u(&Lc[st][row][q * 4]), &g_P[6][b * NS + i0 + row][kc + q * 4]);
        } else if (t < 192) {
            int tt = t - 128, row = tt >> 3, q = tt & 7;
            cpa16(s2u(&Rc[st][row][q * 4]), &g_P[7][b * NS + j0 + row][kc + q * 4]);
        }
        { int row = t >> 2, q = (t & 3) * 8;
          cpa16(s2u(&W2h[st][row][q]), &g_W2thi[row][kc + q]);
          cpa16(s2u(&W2l[st][row][q]), &g_W2tlo[row][kc + q]); }
        cpcommit();
    };

    load_chunk(0, 0);
    const int NCH = NL / 32;
    for (int c = 0; c < NCH; c++) {
        const int st = c & 1;
        if (c + 1 < NCH) { load_chunk((c + 1) * 32, (c + 1) & 1); cpwait1(); }
        else cpwait0();
        __syncthreads();
        // tanh + split -> H tiles
        {
            const float* Lr = &Lc[st][p >> 3][kh * 16];
            const float* Rr = &Rc[st][p & 7][kh * 16];
            uint32_t hv[8], lv[8];
#pragma unroll
            for (int q = 0; q < 4; q++) {
                float4 lx = *(const float4*)&Lr[q * 4];
                float4 rx = *(const float4*)&Rr[q * 4];
                float h0 = tanha(lx.x + rx.x), h1 = tanha(lx.y + rx.y);
                float h2 = tanha(lx.z + rx.z), h3 = tanha(lx.w + rx.w);
                float g0 = __bfloat162float(__float2bfloat16(h0));
                float g1 = __bfloat162float(__float2bfloat16(h1));
                float g2 = __bfloat162float(__float2bfloat16(h2));
                float g3 = __bfloat162float(__float2bfloat16(h3));
                hv[q*2]   = pack_bf2(h0, h1);
                hv[q*2+1] = pack_bf2(h2, h3);
                lv[q*2]   = pack_bf2(h0 - g0, h1 - g1);
                lv[q*2+1] = pack_bf2(h2 - g2, h3 - g3);
            }
            *(uint4*)&Hh[p][kh * 16]     = make_uint4(hv[0], hv[1], hv[2], hv[3]);
            *(uint4*)&Hh[p][kh * 16 + 8] = make_uint4(hv[4], hv[5], hv[6], hv[7]);
            *(uint4*)&Hl[p][kh * 16]     = make_uint4(lv[0], lv[1], lv[2], lv[3]);
            *(uint4*)&Hl[p][kh * 16 + 8] = make_uint4(lv[4], lv[5], lv[6], lv[7]);
        }
        __syncthreads();
#pragma unroll
        for (int ks = 0; ks < 2; ks++) {
            const int k0 = ks * 16;
            uint32_t ah[4][4], al[4][4], bh[2][2], bl[2][2];
#pragma unroll
            for (int mt = 0; mt < 4; mt++) {
                int ar = wm * 64 + mt * 16 + (lane & 15), ac = k0 + ((lane >> 4) << 3);
                ldm4(ah[mt], s2u(&Hh[ar][ac]));
                ldm4(al[mt], s2u(&Hl[ar][ac]));
            }
            {
                int br = wn * 16 + ((lane >> 4) << 3) + (lane & 7);
                int bc = k0 + (((lane >> 3) & 1) << 3);
                uint32_t r[4];
                ldm4(r, s2u(&W2h[st][br][bc]));
                bh[0][0]=r[0]; bh[0][1]=r[1]; bh[1][0]=r[2]; bh[1][1]=r[3];
                ldm4(r, s2u(&W2l[st][br][bc]));
                bl[0][0]=r[0]; bl[0][1]=r[1]; bl[1][0]=r[2]; bl[1][1]=r[3];
            }
#pragma unroll
            for (int mt = 0; mt < 4; mt++)
#pragma unroll
                for (int nt = 0; nt < 2; nt++) {
                    mma_bb(acc[mt][nt], ah[mt], bh[nt]);
                    mma_bb(acc[mt][nt], ah[mt], bl[nt]);
                    mma_bb(acc[mt][nt], al[mt], bh[nt]);
                }
        }
        __syncthreads();
    }
#pragma unroll
    for (int mt = 0; mt < 4; mt++)
#pragma unroll
        for (int nt = 0; nt < 2; nt++) {
            int o = wn * 16 + nt * 8 + ((lane & 3) << 1);
            if (o < NR) {
                float bb0 = __ldg(&b2[o]), bb1 = __ldg(&b2[o + 1]);
#pragma unroll
                for (int half = 0; half < 2; half++) {
                    int pp = wm * 64 + mt * 16 + (lane >> 2) + half * 8;
                    int i = i0 + (pp >> 3), j = j0 + (pp & 7);
                    float2 v = make_float2(acc[mt][nt][half*2] + bb0,
                                           acc[mt][nt][half*2+1] + bb1);
                    *(float2*)&out[((b * NS + i) * NS + j) * NR + o] = v;
                }
            }
        }
}

// ---------------- scalar pair heads ----------------
__global__ __launch_bounds__(256) void pair_scalar_kernel(ScalArgs sa, float* __restrict__ out) {
    const int head = blockIdx.z, b = blockIdx.y;
    const int it = blockIdx.x >> 2, jt = blockIdx.x & 3;
    if (head == 0 && it * 64 + 63 < jt * 32) return;
    const int i0 = it * 64, j0 = jt * 32;
    __shared__ float Ls[32][68];
    __shared__ float Rs[32][36];
    __shared__ float w2s[32];
    const float* __restrict__ Lg = &g_P[head * 2][b * NS + i0][0];
    const float* __restrict__ Rg = &g_P[head * 2 + 1][b * NS + j0][0];
    const float* __restrict__ w2 = sa.w2[head];
    const int t = threadIdx.x;
    const int ti4 = (t >> 4) << 2, tj2 = (t & 15) << 1;
    float acc[4][2];
#pragma unroll
    for (int r = 0; r < 4; r++) { acc[r][0] = 0.f; acc[r][1] = 0.f; }
    for (int l0 = 0; l0 < NL; l0 += 32) {
#pragma unroll
        for (int m = 0; m < 8; m++) {
            int e = t + 256 * m, lk = e & 31, i = e >> 5;
            Ls[lk][i] = Lg[i * NL + l0 + lk];
        }
#pragma unroll
        for (int m = 0; m < 4; m++) {
            int e = t + 256 * m, lk = e & 31, j = e >> 5;
            Rs[lk][j] = Rg[j * NL + l0 + lk];
        }
        if (t < 32) w2s[t] = w2[l0 + t];
        __syncthreads();
#pragma unroll
        for (int lk = 0; lk < 32; lk++) {
            float4 xv = *(const float4*)&Ls[lk][ti4];
            float2 yv = *(const float2*)&Rs[lk][tj2];
            float wv = w2s[lk];
            float xs[4] = {xv.x, xv.y, xv.z, xv.w};
#pragma unroll
            for (int r = 0; r < 4; r++) {
                acc[r][0] = fmaf(tanha(xs[r] + yv.x), wv, acc[r][0]);
                acc[r][1] = fmaf(tanha(xs[r] + yv.y), wv, acc[r][1]);
            }
        }
        __syncthreads();
    }
    const float bb = sa.b2[head][0];
    float* o = out + head * OUT_HEAD + b * NS * NS;
#pragma unroll
    for (int r = 0; r < 4; r++) {
        o[(i0 + ti4 + r) * NS + j0 + tj2]     = acc[r][0] + bb;
        o[(i0 + ti4 + r) * NS + j0 + tj2 + 1] = acc[r][1] + bb;
    }
}

__global__ void sym_kernel(float* __restrict__ out) {
    int idx = blockIdx.x * 256 + threadIdx.x;
    int b = idx >> 14, r = idx & 16383, i = r >> 7, j = r & 127;
    if (i < j) out[idx] = out[(b << 14) + (j << 7) + i];
}

// ---------------------------------------------------------------------------
extern "C" void kernel_launch(void* const* d_in, const int* in_sizes, int n_in,
                              void* d_out, int out_size) {
    (void)in_sizes; (void)n_in; (void)out_size;
    const float* x = (const float*)d_in[0];
    ProjArgs pa;
    pa.W1[0] = (const float*)d_in[1];  pa.b1[0] = (const float*)d_in[2];
    pa.W1[1] = (const float*)d_in[5];  pa.b1[1] = (const float*)d_in[6];
    pa.W1[2] = (const float*)d_in[9];  pa.b1[2] = (const float*)d_in[10];
    pa.W1[3] = (const float*)d_in[13]; pa.b1[3] = (const float*)d_in[14];
    ScalArgs sa;
    sa.w2[0] = (const float*)d_in[3];  sa.b2[0] = (const float*)d_in[4];
    sa.w2[1] = (const float*)d_in[7];  sa.b2[1] = (const float*)d_in[8];
    sa.w2[2] = (const float*)d_in[11]; sa.b2[2] = (const float*)d_in[12];
    float* out = (float*)d_out;

    static int configured = 0;
    if (!configured) {
        cudaFuncSetAttribute(proj_mma, cudaFuncAttributeMaxDynamicSharedMemorySize,
                             2 * PJ_STAGE * (int)sizeof(__nv_bfloat16));
        configured = 1;
    }

    prep_x<<<2048, 256>>>(x);
    prep_w<<<dim3(16, 16, 8), 256>>>(pa);
    prep_w2<<<128, 256>>>((const float*)d_in[15]);

    proj_mma<<<dim3(8, 4, 8), 256, 2 * PJ_STAGE * (int)sizeof(__nv_bfloat16)>>>(pa);

    pair_scalar_kernel<<<dim3(8, 8, 3), 256>>>(sa, out);

    lab_mma<<<dim3(16, 8, 8), 256>>>((const float*)d_in[16], out + 3 * OUT_HEAD);

    sym_kernel<<<512, 256>>>(out);
}

// round 12
// speedup vs baseline: 2.1420x; 1.1425x over previous
#include <cuda_runtime.h>
#include <cuda_bf16.h>
#include <stdint.h>

#define NB 8
#define NS 128
#define ND 512
#define NL 512
#define NR 50
#define NBS 1024
#define OUT_HEAD (NB*NS*NS)

__device__ __align__(1024) float g_P[8][NBS][NL];
__device__ __align__(1024) __nv_bfloat16 g_Xhi[NBS][ND];
__device__ __align__(1024) __nv_bfloat16 g_Xlo[NBS][ND];
__device__ __align__(1024) __nv_bfloat16 g_Wthi[8][NL][ND];   // [z][n][k]
__device__ __align__(1024) __nv_bfloat16 g_Wtlo[8][NL][ND];
__device__ __align__(1024) __nv_bfloat16 g_W2thi[64][NL];     // [o][l], o padded to 64
__device__ __align__(1024) __nv_bfloat16 g_W2tlo[64][NL];

struct ProjArgs { const float* W1[4]; const float* b1[4]; };
struct ScalArgs { const float* w2[3]; const float* b2[3]; };

__device__ __forceinline__ float tanha(float x) {
    float y; asm("tanh.approx.f32 %0, %1;" : "=f"(y) : "f"(x)); return y;
}
__device__ __forceinline__ uint32_t s2u(const void* p) {
    uint32_t a;
    asm("{ .reg .u64 t; cvta.to.shared.u64 t, %1; cvt.u32.u64 %0, t; }" : "=r"(a) : "l"(p));
    return a;
}
__device__ __forceinline__ void ldm4(uint32_t* r, uint32_t a) {
    asm volatile("ldmatrix.sync.aligned.m8n8.x4.shared.b16 {%0,%1,%2,%3}, [%4];"
        : "=r"(r[0]), "=r"(r[1]), "=r"(r[2]), "=r"(r[3]) : "r"(a));
}
__device__ __forceinline__ void mma_bb(float* c, const uint32_t* a, const uint32_t* b) {
    asm volatile("mma.sync.aligned.m16n8k16.row.col.f32.bf16.bf16.f32 "
        "{%0,%1,%2,%3}, {%4,%5,%6,%7}, {%8,%9}, {%0,%1,%2,%3};"
        : "+f"(c[0]), "+f"(c[1]), "+f"(c[2]), "+f"(c[3])
        : "r"(a[0]), "r"(a[1]), "r"(a[2]), "r"(a[3]), "r"(b[0]), "r"(b[1]));
}
__device__ __forceinline__ void cpa16(uint32_t s, const void* g) {
    asm volatile("cp.async.ca.shared.global [%0], [%1], 16;" :: "r"(s), "l"(g));
}
__device__ __forceinline__ void cpcommit() {
    asm volatile("cp.async.commit_group;" ::: "memory");
}
__device__ __forceinline__ void cpwait1() {
    asm volatile("cp.async.wait_group 1;" ::: "memory");
}
__device__ __forceinline__ void cpwait0() {
    asm volatile("cp.async.wait_group 0;" ::: "memory");
}
__device__ __forceinline__ uint32_t pack_bf2(float a, float b) {
    return ((uint32_t)__bfloat16_as_ushort(__float2bfloat16(b)) << 16)
         | (uint32_t)__bfloat16_as_ushort(__float2bfloat16(a));
}

// ---------------- prep: fp32 -> split bf16 ----------------
__global__ void prep_x(const float* __restrict__ x) {
    int i = blockIdx.x * 256 + threadIdx.x;
    float v = x[i];
    __nv_bfloat16 h = __float2bfloat16(v);
    (&g_Xhi[0][0])[i] = h;
    (&g_Xlo[0][0])[i] = __float2bfloat16(v - __bfloat162float(h));
}
__global__ void prep_w(ProjArgs pa) {
    __shared__ float tile[32][33];
    int z = blockIdx.z, head = z >> 1, side = z & 1;
    int k0 = blockIdx.x * 32, n0 = blockIdx.y * 32;
    const float* W = pa.W1[head] + side * ND * NL;
    int t = threadIdx.x, c = t & 31, r4 = (t >> 5) * 4;
#pragma unroll
    for (int q = 0; q < 4; q++) tile[r4 + q][c] = W[(k0 + r4 + q) * NL + n0 + c];
    __syncthreads();
#pragma unroll
    for (int q = 0; q < 4; q++) {
        float v = tile[c][r4 + q];
        __nv_bfloat16 h = __float2bfloat16(v);
        g_Wthi[z][n0 + r4 + q][k0 + c] = h;
        g_Wtlo[z][n0 + r4 + q][k0 + c] = __float2bfloat16(v - __bfloat162float(h));
    }
}
__global__ void prep_w2(const float* __restrict__ W2) {
    int e = blockIdx.x * 256 + threadIdx.x;   // 64*512
    int o = e >> 9, l = e & 511;
    float v = (o < NR) ? W2[l * NR + o] : 0.f;
    __nv_bfloat16 h = __float2bfloat16(v);
    g_W2thi[o][l] = h;
    g_W2tlo[o][l] = __float2bfloat16(v - __bfloat162float(h));
}

// ---------------- projections via mma.sync, 2-stage pipeline ----------------
// grid (8 Mtile, 4 Ntile, 8 z), 256 thr. CTA 128x128, warp 64x32, K chunks of 32.
#define PAD 40
#define PJ_STAGE 20480   // bf16 elements per stage (4 tiles of 128*PAD)
__global__ __launch_bounds__(256, 2) void proj_mma(ProjArgs pa) {
    extern __shared__ __nv_bfloat16 dsm[];
    const int t = threadIdx.x, lane = t & 31, w = t >> 5;
    const int wm = w >> 2, wn = w & 3;          // warp grid 2x4
    const int z = blockIdx.z, head = z >> 1, side = z & 1;
    const int r0 = blockIdx.x * 128, c0 = blockIdx.y * 128;
    const float* __restrict__ b1p = pa.b1[head];

    float acc[4][4][4];
#pragma unroll
    for (int mt = 0; mt < 4; mt++)
#pragma unroll
        for (int nt = 0; nt < 4; nt++) { acc[mt][nt][0]=0.f; acc[mt][nt][1]=0.f; acc[mt][nt][2]=0.f; acc[mt][nt][3]=0.f; }

    const int lrow = t >> 2, lq = (t & 3) * 8;

    auto load_chunk = [&](int kc, int st) {
        __nv_bfloat16* Ah = dsm + st * PJ_STAGE;
        __nv_bfloat16* Al = Ah + 5120;
        __nv_bfloat16* Bh = Ah + 10240;
        __nv_bfloat16* Bl = Ah + 15360;
#pragma unroll
        for (int m = 0; m < 2; m++) {
            int row = lrow + 64 * m;
            cpa16(s2u(Ah + row * PAD + lq), &g_Xhi[r0 + row][kc + lq]);
            cpa16(s2u(Al + row * PAD + lq), &g_Xlo[r0 + row][kc + lq]);
            cpa16(s2u(Bh + row * PAD + lq), &g_Wthi[z][c0 + row][kc + lq]);
            cpa16(s2u(Bl + row * PAD + lq), &g_Wtlo[z][c0 + row][kc + lq]);
        }
        cpcommit();
    };

    load_chunk(0, 0);
    const int NCH = ND / 32;
    for (int c = 0; c < NCH; c++) {
        if (c + 1 < NCH) { load_chunk((c + 1) * 32, (c + 1) & 1); cpwait1(); }
        else cpwait0();
        __syncthreads();
        const __nv_bfloat16* Ah = dsm + (c & 1) * PJ_STAGE;
        const __nv_bfloat16* Al = Ah + 5120;
        const __nv_bfloat16* Bh = Ah + 10240;
        const __nv_bfloat16* Bl = Ah + 15360;
#pragma unroll
        for (int ks = 0; ks < 2; ks++) {
            const int k0 = ks * 16;
            uint32_t ah[4][4], al[4][4], bh[4][2], bl[4][2];
#pragma unroll
            for (int mt = 0; mt < 4; mt++) {
                int ar = wm * 64 + mt * 16 + (lane & 15), ac = k0 + ((lane >> 4) << 3);
                ldm4(ah[mt], s2u(Ah + ar * PAD + ac));
                ldm4(al[mt], s2u(Al + ar * PAD + ac));
            }
#pragma unroll
            for (int nh = 0; nh < 2; nh++) {
                int br = wn * 32 + nh * 16 + ((lane >> 4) << 3) + (lane & 7);
                int bc = k0 + (((lane >> 3) & 1) << 3);
                uint32_t r[4];
                ldm4(r, s2u(Bh + br * PAD + bc));
                bh[nh*2][0]=r[0]; bh[nh*2][1]=r[1]; bh[nh*2+1][0]=r[2]; bh[nh*2+1][1]=r[3];
                ldm4(r, s2u(Bl + br * PAD + bc));
                bl[nh*2][0]=r[0]; bl[nh*2][1]=r[1]; bl[nh*2+1][0]=r[2]; bl[nh*2+1][1]=r[3];
            }
#pragma unroll
            for (int mt = 0; mt < 4; mt++)
#pragma unroll
                for (int nt = 0; nt < 4; nt++) {
                    mma_bb(acc[mt][nt], ah[mt], bh[nt]);
                    mma_bb(acc[mt][nt], ah[mt], bl[nt]);
                    mma_bb(acc[mt][nt], al[mt], bh[nt]);
                }
        }
        __syncthreads();
    }
#pragma unroll
    for (int mt = 0; mt < 4; mt++)
#pragma unroll
        for (int nt = 0; nt < 4; nt++) {
            int row = r0 + wm * 64 + mt * 16 + (lane >> 2);
            int col = c0 + wn * 32 + nt * 8 + ((lane & 3) << 1);
            float bb0 = 0.f, bb1 = 0.f;
            if (side) { bb0 = __ldg(&b1p[col]); bb1 = __ldg(&b1p[col + 1]); }
            float2 v0 = make_float2(acc[mt][nt][0] + bb0, acc[mt][nt][1] + bb1);
            float2 v1 = make_float2(acc[mt][nt][2] + bb0, acc[mt][nt][3] + bb1);
            *(float2*)&g_P[z][row][col] = v0;
            *(float2*)&g_P[z][row + 8][col] = v1;
        }
}

// ---------------- fused pair-scalar + lab kernel ----------------
// grid (16, 8, 11): z<3 -> scalar pair head z; z>=3 -> lab batch b=z-3.
// Shared smem union: lab needs 47872 B, pair needs 13440 B.
#define SM_BYTES 47872
// lab offsets within the union
#define O_LC   0          // float [2][16][36] = 4608
#define O_RC   4608       // float [2][8][36]  = 2304
#define O_W2H  6912       // bf16 [2][64][40]  = 10240
#define O_W2L  17152      // bf16 [2][64][40]  = 10240
#define O_HH   27392      // bf16 [128][40]    = 10240
#define O_HL   37632      // bf16 [128][40]    = 10240

__global__ __launch_bounds__(256) void pairlab_kernel(ScalArgs sa,
                                                      const float* __restrict__ b2lab,
                                                      float* __restrict__ out) {
    __shared__ __align__(16) char sraw[SM_BYTES];
    const int t = threadIdx.x;

    if (blockIdx.z < 3) {
        // ---------------- pair-scalar branch ----------------
        if (blockIdx.x >= 8) return;
        const int head = blockIdx.z, b = blockIdx.y;
        const int it = blockIdx.x >> 2, jt = blockIdx.x & 3;
        if (head == 0 && it * 64 + 63 < jt * 32) return;
        const int i0 = it * 64, j0 = jt * 32;
        float (*Ls)[68] = (float(*)[68])sraw;                 // 8704
        float (*Rs)[36] = (float(*)[36])(sraw + 8704);        // 4608
        float* w2s = (float*)(sraw + 13312);                  // 128
        const float* __restrict__ Lg = &g_P[head * 2][b * NS + i0][0];
        const float* __restrict__ Rg = &g_P[head * 2 + 1][b * NS + j0][0];
        const float* __restrict__ w2 = sa.w2[head];
        const int ti4 = (t >> 4) << 2, tj2 = (t & 15) << 1;
        float acc[4][2];
#pragma unroll
        for (int r = 0; r < 4; r++) { acc[r][0] = 0.f; acc[r][1] = 0.f; }
        for (int l0 = 0; l0 < NL; l0 += 32) {
#pragma unroll
            for (int m = 0; m < 8; m++) {
                int e = t + 256 * m, lk = e & 31, i = e >> 5;
                Ls[lk][i] = Lg[i * NL + l0 + lk];
            }
#pragma unroll
            for (int m = 0; m < 4; m++) {
                int e = t + 256 * m, lk = e & 31, j = e >> 5;
                Rs[lk][j] = Rg[j * NL + l0 + lk];
            }
            if (t < 32) w2s[t] = w2[l0 + t];
            __syncthreads();
#pragma unroll
            for (int lk = 0; lk < 32; lk++) {
                float4 xv = *(const float4*)&Ls[lk][ti4];
                float2 yv = *(const float2*)&Rs[lk][tj2];
                float wv = w2s[lk];
                float xs[4] = {xv.x, xv.y, xv.z, xv.w};
#pragma unroll
                for (int r = 0; r < 4; r++) {
                    acc[r][0] = fmaf(tanha(xs[r] + yv.x), wv, acc[r][0]);
                    acc[r][1] = fmaf(tanha(xs[r] + yv.y), wv, acc[r][1]);
                }
            }
            __syncthreads();
        }
        const float bb = sa.b2[head][0];
        float* o = out + head * OUT_HEAD + b * NS * NS;
#pragma unroll
        for (int r = 0; r < 4; r++) {
            o[(i0 + ti4 + r) * NS + j0 + tj2]     = acc[r][0] + bb;
            o[(i0 + ti4 + r) * NS + j0 + tj2 + 1] = acc[r][1] + bb;
        }
        return;
    }

    // ---------------- lab branch ----------------
    const int lane = t & 31, w = t >> 5;
    const int wm = w >> 2, wn = w & 3;          // warp grid 2x4, warp tile 64x16
    const int b = blockIdx.z - 3, i0 = blockIdx.y * 16, j0 = blockIdx.x * 8;
    float* outl = out + 3 * OUT_HEAD;           // labels region (fixes round-10 bug)
    float* Lc = (float*)(sraw + O_LC);                        // [st][row][36]
    float* Rc = (float*)(sraw + O_RC);                        // [st][row][36]
    __nv_bfloat16* W2h = (__nv_bfloat16*)(sraw + O_W2H);      // [st][64][40]
    __nv_bfloat16* W2l = (__nv_bfloat16*)(sraw + O_W2L);
    __nv_bfloat16* Hh = (__nv_bfloat16*)(sraw + O_HH);        // [128][40]
    __nv_bfloat16* Hl = (__nv_bfloat16*)(sraw + O_HL);

    float acc[4][2][4];
#pragma unroll
    for (int mt = 0; mt < 4; mt++)
#pragma unroll
        for (int nt = 0; nt < 2; nt++) { acc[mt][nt][0]=0.f; acc[mt][nt][1]=0.f; acc[mt][nt][2]=0.f; acc[mt][nt][3]=0.f; }

    const int p = t >> 1, kh = t & 1;           // tanh producer: pair, k-half

    auto load_chunk = [&](int kc, int st) {
        if (t < 128) {
            int row = t >> 3, q = t & 7;
            cpa16(s2u(Lc + st * 576 + row * 36 + q * 4), &g_P[6][b * NS + i0 + row][kc + q * 4]);
        } else if (t < 192) {
            int tt = t - 128, row = tt >> 3, q = tt & 7;
            cpa16(s2u(Rc + st * 288 + row * 36 + q * 4), &g_P[7][b * NS + j0 + row][kc + q * 4]);
        }
        { int row = t >> 2, q = (t & 3) * 8;
          cpa16(s2u(W2h + st * 2560 + row * PAD + q), &g_W2thi[row][kc + q]);
          cpa16(s2u(W2l + st * 2560 + row * PAD + q), &g_W2tlo[row][kc + q]); }
        cpcommit();
    };

    load_chunk(0, 0);
    const int NCH = NL / 32;
    for (int c = 0; c < NCH; c++) {
        const int st = c & 1;
        if (c + 1 < NCH) { load_chunk((c + 1) * 32, (c + 1) & 1); cpwait1(); }
        else cpwait0();
        __syncthreads();
        // tanh + split -> H tiles
        {
            const float* Lr = Lc + st * 576 + (p >> 3) * 36 + kh * 16;
            const float* Rr = Rc + st * 288 + (p & 7) * 36 + kh * 16;
            uint32_t hv[8], lv[8];
#pragma unroll
            for (int q = 0; q < 4; q++) {
                float4 lx = *(const float4*)&Lr[q * 4];
                float4 rx = *(const float4*)&Rr[q * 4];
                float h0 = tanha(lx.x + rx.x), h1 = tanha(lx.y + rx.y);
                float h2 = tanha(lx.z + rx.z), h3 = tanha(lx.w + rx.w);
                float g0 = __bfloat162float(__float2bfloat16(h0));
                float g1 = __bfloat162float(__float2bfloat16(h1));
                float g2 = __bfloat162float(__float2bfloat16(h2));
                float g3 = __bfloat162float(__float2bfloat16(h3));
                hv[q*2]   = pack_bf2(h0, h1);
                hv[q*2+1] = pack_bf2(h2, h3);
                lv[q*2]   = pack_bf2(h0 - g0, h1 - g1);
                lv[q*2+1] = pack_bf2(h2 - g2, h3 - g3);
            }
            *(uint4*)(Hh + p * PAD + kh * 16)     = make_uint4(hv[0], hv[1], hv[2], hv[3]);
            *(uint4*)(Hh + p * PAD + kh * 16 + 8) = make_uint4(hv[4], hv[5], hv[6], hv[7]);
            *(uint4*)(Hl + p * PAD + kh * 16)     = make_uint4(lv[0], lv[1], lv[2], lv[3]);
            *(uint4*)(Hl + p * PAD + kh * 16 + 8) = make_uint4(lv[4], lv[5], lv[6], lv[7]);
        }
        __syncthreads();
#pragma unroll
        for (int ks = 0; ks < 2; ks++) {
            const int k0 = ks * 16;
            uint32_t ah[4][4], al[4][4], bh[2][2], bl[2][2];
#pragma unroll
            for (int mt = 0; mt < 4; mt++) {
                int ar = wm * 64 + mt * 16 + (lane & 15), ac = k0 + ((lane >> 4) << 3);
                ldm4(ah[mt], s2u(Hh + ar * PAD + ac));
                ldm4(al[mt], s2u(Hl + ar * PAD + ac));
            }
            {
                int br = wn * 16 + ((lane >> 4) << 3) + (lane & 7);
                int bc = k0 + (((lane >> 3) & 1) << 3);
                uint32_t r[4];
                ldm4(r, s2u(W2h + st * 2560 + br * PAD + bc));
                bh[0][0]=r[0]; bh[0][1]=r[1]; bh[1][0]=r[2]; bh[1][1]=r[3];
                ldm4(r, s2u(W2l + st * 2560 + br * PAD + bc));
                bl[0][0]=r[0]; bl[0][1]=r[1]; bl[1][0]=r[2]; bl[1][1]=r[3];
            }
#pragma unroll
            for (int mt = 0; mt < 4; mt++)
#pragma unroll
                for (int nt = 0; nt < 2; nt++) {
                    mma_bb(acc[mt][nt], ah[mt], bh[nt]);
                    mma_bb(acc[mt][nt], ah[mt], bl[nt]);
                    mma_bb(acc[mt][nt], al[mt], bh[nt]);
                }
        }
        __syncthreads();
    }
#pragma unroll
    for (int mt = 0; mt < 4; mt++)
#pragma unroll
        for (int nt = 0; nt < 2; nt++) {
            int o = wn * 16 + nt * 8 + ((lane & 3) << 1);
            if (o < NR) {
                float bb0 = __ldg(&b2lab[o]), bb1 = __ldg(&b2lab[o + 1]);
#pragma unroll
                for (int half = 0; half < 2; half++) {
                    int pp = wm * 64 + mt * 16 + (lane >> 2) + half * 8;
                    int i = i0 + (pp >> 3), j = j0 + (pp & 7);
                    float2 v = make_float2(acc[mt][nt][half*2] + bb0,
                                           acc[mt][nt][half*2+1] + bb1);
                    *(float2*)&outl[((b * NS + i) * NS + j) * NR + o] = v;
                }
            }
        }
}

__global__ void sym_kernel(float* __restrict__ out) {
    int idx = blockIdx.x * 256 + threadIdx.x;
    int b = idx >> 14, r = idx & 16383, i = r >> 7, j = r & 127;
    if (i < j) out[idx] = out[(b << 14) + (j << 7) + i];
}

// ---------------------------------------------------------------------------
extern "C" void kernel_launch(void* const* d_in, const int* in_sizes, int n_in,
                              void* d_out, int out_size) {
    (void)in_sizes; (void)n_in; (void)out_size;
    const float* x = (const float*)d_in[0];
    ProjArgs pa;
    pa.W1[0] = (const float*)d_in[1];  pa.b1[0] = (const float*)d_in[2];
    pa.W1[1] = (const float*)d_in[5];  pa.b1[1] = (const float*)d_in[6];
    pa.W1[2] = (const float*)d_in[9];  pa.b1[2] = (const float*)d_in[10];
    pa.W1[3] = (const float*)d_in[13]; pa.b1[3] = (const float*)d_in[14];
    ScalArgs sa;
    sa.w2[0] = (const float*)d_in[3];  sa.b2[0] = (const float*)d_in[4];
    sa.w2[1] = (const float*)d_in[7];  sa.b2[1] = (const float*)d_in[8];
    sa.w2[2] = (const float*)d_in[11]; sa.b2[2] = (const float*)d_in[12];
    float* out = (float*)d_out;

    static int configured = 0;
    if (!configured) {
        cudaFuncSetAttribute(proj_mma, cudaFuncAttributeMaxDynamicSharedMemorySize,
                             2 * PJ_STAGE * (int)sizeof(__nv_bfloat16));
        configured = 1;
    }

    prep_x<<<2048, 256>>>(x);
    prep_w<<<dim3(16, 16, 8), 256>>>(pa);
    prep_w2<<<128, 256>>>((const float*)d_in[15]);

    proj_mma<<<dim3(8, 4, 8), 256, 2 * PJ_STAGE * (int)sizeof(__nv_bfloat16)>>>(pa);

    pairlab_kernel<<<dim3(16, 8, 11), 256>>>(sa, (const float*)d_in[16], out);

    sym_kernel<<<512, 256>>>(out);
}

// round 16
// speedup vs baseline: 2.2196x; 1.0362x over previous
#include <cuda_runtime.h>
#include <cuda_bf16.h>
#include <stdint.h>

#define NB 8
#define NS 128
#define ND 512
#define NL 512
#define NR 50
#define NBS 1024
#define OUT_HEAD (NB*NS*NS)

__device__ __align__(1024) float g_P[8][NBS][NL];
__device__ __align__(1024) __nv_bfloat16 g_Xhi[NBS][ND];
__device__ __align__(1024) __nv_bfloat16 g_Xlo[NBS][ND];
__device__ __align__(1024) __nv_bfloat16 g_Wthi[8][NL][ND];   // [z][n][k]
__device__ __align__(1024) __nv_bfloat16 g_Wtlo[8][NL][ND];
__device__ __align__(1024) __nv_bfloat16 g_W2thi[64][NL];     // [o][l], o padded to 64
__device__ __align__(1024) __nv_bfloat16 g_W2tlo[64][NL];

struct ProjArgs { const float* W1[4]; const float* b1[4]; };
struct ScalArgs { const float* w2[3]; const float* b2[3]; };

__device__ __forceinline__ float tanha(float x) {
    float y; asm("tanh.approx.f32 %0, %1;" : "=f"(y) : "f"(x)); return y;
}
__device__ __forceinline__ uint32_t s2u(const void* p) {
    uint32_t a;
    asm("{ .reg .u64 t; cvta.to.shared.u64 t, %1; cvt.u32.u64 %0, t; }" : "=r"(a) : "l"(p));
    return a;
}
__device__ __forceinline__ void ldm4(uint32_t* r, uint32_t a) {
    asm volatile("ldmatrix.sync.aligned.m8n8.x4.shared.b16 {%0,%1,%2,%3}, [%4];"
        : "=r"(r[0]), "=r"(r[1]), "=r"(r[2]), "=r"(r[3]) : "r"(a));
}
__device__ __forceinline__ void mma_bb(float* c, const uint32_t* a, const uint32_t* b) {
    asm volatile("mma.sync.aligned.m16n8k16.row.col.f32.bf16.bf16.f32 "
        "{%0,%1,%2,%3}, {%4,%5,%6,%7}, {%8,%9}, {%0,%1,%2,%3};"
        : "+f"(c[0]), "+f"(c[1]), "+f"(c[2]), "+f"(c[3])
        : "r"(a[0]), "r"(a[1]), "r"(a[2]), "r"(a[3]), "r"(b[0]), "r"(b[1]));
}
__device__ __forceinline__ void cpa16(uint32_t s, const void* g) {
    asm volatile("cp.async.ca.shared.global [%0], [%1], 16;" :: "r"(s), "l"(g));
}
__device__ __forceinline__ void cpcommit() {
    asm volatile("cp.async.commit_group;" ::: "memory");
}
__device__ __forceinline__ void cpwait1() {
    asm volatile("cp.async.wait_group 1;" ::: "memory");
}
__device__ __forceinline__ void cpwait0() {
    asm volatile("cp.async.wait_group 0;" ::: "memory");
}
// packed bf16x2 = {lo=a, hi=b}, round-to-nearest-even
__device__ __forceinline__ uint32_t cvt_bf2(float a, float b) {
    uint32_t r;
    asm("cvt.rn.bf16x2.f32 %0, %1, %2;" : "=r"(r) : "f"(b), "f"(a));
    return r;
}

// ---------------- prep: fp32 -> split bf16 ----------------
__global__ void prep_x(const float* __restrict__ x) {
    int i = blockIdx.x * 256 + threadIdx.x;
    float v = x[i];
    __nv_bfloat16 h = __float2bfloat16(v);
    (&g_Xhi[0][0])[i] = h;
    (&g_Xlo[0][0])[i] = __float2bfloat16(v - __bfloat162float(h));
}
__global__ void prep_w(ProjArgs pa) {
    __shared__ float tile[32][33];
    int z = blockIdx.z, head = z >> 1, side = z & 1;
    int k0 = blockIdx.x * 32, n0 = blockIdx.y * 32;
    const float* W = pa.W1[head] + side * ND * NL;
    int t = threadIdx.x, c = t & 31, r4 = (t >> 5) * 4;
#pragma unroll
    for (int q = 0; q < 4; q++) tile[r4 + q][c] = W[(k0 + r4 + q) * NL + n0 + c];
    __syncthreads();
#pragma unroll
    for (int q = 0; q < 4; q++) {
        float v = tile[c][r4 + q];
        __nv_bfloat16 h = __float2bfloat16(v);
        g_Wthi[z][n0 + r4 + q][k0 + c] = h;
        g_Wtlo[z][n0 + r4 + q][k0 + c] = __float2bfloat16(v - __bfloat162float(h));
    }
}
__global__ void prep_w2(const float* __restrict__ W2) {
    int e = blockIdx.x * 256 + threadIdx.x;   // 64*512
    int o = e >> 9, l = e & 511;
    float v = (o < NR) ? W2[l * NR + o] : 0.f;
    __nv_bfloat16 h = __float2bfloat16(v);
    g_W2thi[o][l] = h;
    g_W2tlo[o][l] = __float2bfloat16(v - __bfloat162float(h));
}

// ---------------- projections via mma.sync, 2-stage pipeline ----------------
// grid (8 Mtile, 4 Ntile, 8 z), 256 thr. CTA 128x128, warp 64x32, K chunks of 32.
#define PAD 40
#define PJ_STAGE 20480   // bf16 elements per stage (4 tiles of 128*PAD)
__global__ __launch_bounds__(256, 2) void proj_mma(ProjArgs pa) {
    extern __shared__ __nv_bfloat16 dsm[];
    const int t = threadIdx.x, lane = t & 31, w = t >> 5;
    const int wm = w >> 2, wn = w & 3;          // warp grid 2x4
    const int z = blockIdx.z, head = z >> 1, side = z & 1;
    const int r0 = blockIdx.x * 128, c0 = blockIdx.y * 128;
    const float* __restrict__ b1p = pa.b1[head];

    float acc[4][4][4];
#pragma unroll
    for (int mt = 0; mt < 4; mt++)
#pragma unroll
        for (int nt = 0; nt < 4; nt++) { acc[mt][nt][0]=0.f; acc[mt][nt][1]=0.f; acc[mt][nt][2]=0.f; acc[mt][nt][3]=0.f; }

    const int lrow = t >> 2, lq = (t & 3) * 8;

    auto load_chunk = [&](int kc, int st) {
        __nv_bfloat16* Ah = dsm + st * PJ_STAGE;
        __nv_bfloat16* Al = Ah + 5120;
        __nv_bfloat16* Bh = Ah + 10240;
        __nv_bfloat16* Bl = Ah + 15360;
#pragma unroll
        for (int m = 0; m < 2; m++) {
            int row = lrow + 64 * m;
            cpa16(s2u(Ah + row * PAD + lq), &g_Xhi[r0 + row][kc + lq]);
            cpa16(s2u(Al + row * PAD + lq), &g_Xlo[r0 + row][kc + lq]);
            cpa16(s2u(Bh + row * PAD + lq), &g_Wthi[z][c0 + row][kc + lq]);
            cpa16(s2u(Bl + row * PAD + lq), &g_Wtlo[z][c0 + row][kc + lq]);
        }
        cpcommit();
    };

    load_chunk(0, 0);
    const int NCH = ND / 32;
    for (int c = 0; c < NCH; c++) {
        if (c + 1 < NCH) { load_chunk((c + 1) * 32, (c + 1) & 1); cpwait1(); }
        else cpwait0();
        __syncthreads();
        const __nv_bfloat16* Ah = dsm + (c & 1) * PJ_STAGE;
        const __nv_bfloat16* Al = Ah + 5120;
        const __nv_bfloat16* Bh = Ah + 10240;
        const __nv_bfloat16* Bl = Ah + 15360;
#pragma unroll
        for (int ks = 0; ks < 2; ks++) {
            const int k0 = ks * 16;
            uint32_t ah[4][4], al[4][4], bh[4][2], bl[4][2];
#pragma unroll
            for (int mt = 0; mt < 4; mt++) {
                int ar = wm * 64 + mt * 16 + (lane & 15), ac = k0 + ((lane >> 4) << 3);
                ldm4(ah[mt], s2u(Ah + ar * PAD + ac));
                ldm4(al[mt], s2u(Al + ar * PAD + ac));
            }
#pragma unroll
            for (int nh = 0; nh < 2; nh++) {
                int br = wn * 32 + nh * 16 + ((lane >> 4) << 3) + (lane & 7);
                int bc = k0 + (((lane >> 3) & 1) << 3);
                uint32_t r[4];
                ldm4(r, s2u(Bh + br * PAD + bc));
                bh[nh*2][0]=r[0]; bh[nh*2][1]=r[1]; bh[nh*2+1][0]=r[2]; bh[nh*2+1][1]=r[3];
                ldm4(r, s2u(Bl + br * PAD + bc));
                bl[nh*2][0]=r[0]; bl[nh*2][1]=r[1]; bl[nh*2+1][0]=r[2]; bl[nh*2+1][1]=r[3];
            }
            // term-major: spread RAW chains on accumulators
#pragma unroll
            for (int mt = 0; mt < 4; mt++)
#pragma unroll
                for (int nt = 0; nt < 4; nt++) mma_bb(acc[mt][nt], ah[mt], bh[nt]);
#pragma unroll
            for (int mt = 0; mt < 4; mt++)
#pragma unroll
                for (int nt = 0; nt < 4; nt++) mma_bb(acc[mt][nt], ah[mt], bl[nt]);
#pragma unroll
            for (int mt = 0; mt < 4; mt++)
#pragma unroll
                for (int nt = 0; nt < 4; nt++) mma_bb(acc[mt][nt], al[mt], bh[nt]);
        }
        __syncthreads();
    }
#pragma unroll
    for (int mt = 0; mt < 4; mt++)
#pragma unroll
        for (int nt = 0; nt < 4; nt++) {
            int row = r0 + wm * 64 + mt * 16 + (lane >> 2);
            int col = c0 + wn * 32 + nt * 8 + ((lane & 3) << 1);
            float bb0 = 0.f, bb1 = 0.f;
            if (side) { bb0 = __ldg(&b1p[col]); bb1 = __ldg(&b1p[col + 1]); }
            float2 v0 = make_float2(acc[mt][nt][0] + bb0, acc[mt][nt][1] + bb1);
            float2 v1 = make_float2(acc[mt][nt][2] + bb0, acc[mt][nt][3] + bb1);
            *(float2*)&g_P[z][row][col] = v0;
            *(float2*)&g_P[z][row + 8][col] = v1;
        }
}

// ---------------- fused pair-scalar + lab kernel ----------------
// grid (16, 8, 7): z<4 -> lab (b = z*2 + (y>>2), it = y&3, jt = x);
//                  z>=4 -> scalar pair head z-4 (x<8 used).
// Dynamic smem 72960 B (lab); pair uses first 13440 B.
#define LAB_SMEM 72960
#define O_W2H  0          // bf16 [2][64][40]  = 10240
#define O_W2L  10240      // bf16 [2][64][40]  = 10240
#define O_HH   20480      // bf16 [256][40]    = 20480
#define O_HL   40960      // bf16 [256][40]    = 20480
#define O_LC   61440      // float [2][32][36] = 9216
#define O_RC   70656      // float [2][8][36]  = 2304

__global__ __launch_bounds__(256, 2) void pairlab_kernel(ScalArgs sa,
                                                         const float* __restrict__ b2lab,
                                                         float* __restrict__ out) {
    extern __shared__ __align__(16) char sdyn[];
    const int t = threadIdx.x;

    if (blockIdx.z >= 4) {
        // ---------------- pair-scalar branch ----------------
        if (blockIdx.x >= 8) return;
        const int head = blockIdx.z - 4, b = blockIdx.y;
        const int it = blockIdx.x >> 2, jt = blockIdx.x & 3;
        if (head == 0 && it * 64 + 63 < jt * 32) return;
        const int i0 = it * 64, j0 = jt * 32;
        float (*Ls)[68] = (float(*)[68])sdyn;                 // 8704
        float (*Rs)[36] = (float(*)[36])(sdyn + 8704);        // 4608
        float* w2s = (float*)(sdyn + 13312);                  // 128
        const float* __restrict__ Lg = &g_P[head * 2][b * NS + i0][0];
        const float* __restrict__ Rg = &g_P[head * 2 + 1][b * NS + j0][0];
        const float* __restrict__ w2 = sa.w2[head];
        const int ti4 = (t >> 4) << 2, tj2 = (t & 15) << 1;
        float acc[4][2];
#pragma unroll
        for (int r = 0; r < 4; r++) { acc[r][0] = 0.f; acc[r][1] = 0.f; }
        for (int l0 = 0; l0 < NL; l0 += 32) {
#pragma unroll
            for (int m = 0; m < 8; m++) {
                int e = t + 256 * m, lk = e & 31, i = e >> 5;
                Ls[lk][i] = Lg[i * NL + l0 + lk];
            }
#pragma unroll
            for (int m = 0; m < 4; m++) {
                int e = t + 256 * m, lk = e & 31, j = e >> 5;
                Rs[lk][j] = Rg[j * NL + l0 + lk];
            }
            if (t < 32) w2s[t] = w2[l0 + t];
            __syncthreads();
#pragma unroll
            for (int lk = 0; lk < 32; lk++) {
                float4 xv = *(const float4*)&Ls[lk][ti4];
                float2 yv = *(const float2*)&Rs[lk][tj2];
                float wv = w2s[lk];
                float xs[4] = {xv.x, xv.y, xv.z, xv.w};
#pragma unroll
                for (int r = 0; r < 4; r++) {
                    acc[r][0] = fmaf(tanha(xs[r] + yv.x), wv, acc[r][0]);
                    acc[r][1] = fmaf(tanha(xs[r] + yv.y), wv, acc[r][1]);
                }
            }
            __syncthreads();
        }
        const float bb = sa.b2[head][0];
        float* o = out + head * OUT_HEAD + b * NS * NS;
#pragma unroll
        for (int r = 0; r < 4; r++) {
            o[(i0 + ti4 + r) * NS + j0 + tj2]     = acc[r][0] + bb;
            o[(i0 + ti4 + r) * NS + j0 + tj2 + 1] = acc[r][1] + bb;
        }
        return;
    }

    // ---------------- lab branch: CTA tile 256 pairs x 64 outs ----------------
    const int lane = t & 31, w = t >> 5;
    const int wm = w >> 1, wn = w & 1;          // warp grid 4x2, warp tile 64x32
    const int b = blockIdx.z * 2 + (blockIdx.y >> 2);
    const int i0 = (blockIdx.y & 3) * 32, j0 = blockIdx.x * 8;
    float* outl = out + 3 * OUT_HEAD;
    __nv_bfloat16* W2h = (__nv_bfloat16*)(sdyn + O_W2H);   // [st][64][40]
    __nv_bfloat16* W2l = (__nv_bfloat16*)(sdyn + O_W2L);
    __nv_bfloat16* Hh  = (__nv_bfloat16*)(sdyn + O_HH);    // [256][40]
    __nv_bfloat16* Hl  = (__nv_bfloat16*)(sdyn + O_HL);
    float* Lc = (float*)(sdyn + O_LC);                     // [st][32][36]
    float* Rc = (float*)(sdyn + O_RC);                     // [st][8][36]

    float acc[4][4][4];
#pragma unroll
    for (int mt = 0; mt < 4; mt++)
#pragma unroll
        for (int nt = 0; nt < 4; nt++) { acc[mt][nt][0]=0.f; acc[mt][nt][1]=0.f; acc[mt][nt][2]=0.f; acc[mt][nt][3]=0.f; }

    auto load_chunk = [&](int kc, int st) {
        { int row = t >> 3, q = t & 7;       // Lc: 32 rows x 32 floats
          cpa16(s2u(Lc + st * 1152 + row * 36 + q * 4), &g_P[6][b * NS + i0 + row][kc + q * 4]); }
        if (t < 64) { int row = t >> 3, q = t & 7;
          cpa16(s2u(Rc + st * 288 + row * 36 + q * 4), &g_P[7][b * NS + j0 + row][kc + q * 4]); }
        { int row = t >> 2, q = (t & 3) * 8; // W2: 64 rows x 32 bf16
          cpa16(s2u(W2h + st * 2560 + row * PAD + q), &g_W2thi[row][kc + q]);
          cpa16(s2u(W2l + st * 2560 + row * PAD + q), &g_W2tlo[row][kc + q]); }
        cpcommit();
    };

    load_chunk(0, 0);
    const int NCH = NL / 32;
    for (int c = 0; c < NCH; c++) {
        const int st = c & 1;
        if (c + 1 < NCH) { load_chunk((c + 1) * 32, (c + 1) & 1); cpwait1(); }
        else cpwait0();
        __syncthreads();
        // tanh + split: thread t <-> pair t, 32 k per chunk
        {
            const float* Lr = Lc + st * 1152 + (t >> 3) * 36;
            const float* Rr = Rc + st * 288 + (t & 7) * 36;
#pragma unroll
            for (int qq = 0; qq < 4; qq++) {
                uint32_t hv[4], lv[4];
#pragma unroll
                for (int e2 = 0; e2 < 2; e2++) {
                    int k = qq * 8 + e2 * 4;
                    float4 lx = *(const float4*)&Lr[k];
                    float4 rx = *(const float4*)&Rr[k];
                    float h0 = tanha(lx.x + rx.x), h1 = tanha(lx.y + rx.y);
                    float h2 = tanha(lx.z + rx.z), h3 = tanha(lx.w + rx.w);
                    uint32_t u01 = cvt_bf2(h0, h1);
                    uint32_t u23 = cvt_bf2(h2, h3);
                    float g0 = __uint_as_float(u01 << 16);
                    float g1 = __uint_as_float(u01 & 0xffff0000u);
                    float g2 = __uint_as_float(u23 << 16);
                    float g3 = __uint_as_float(u23 & 0xffff0000u);
                    hv[e2*2]   = u01; hv[e2*2+1] = u23;
                    lv[e2*2]   = cvt_bf2(h0 - g0, h1 - g1);
                    lv[e2*2+1] = cvt_bf2(h2 - g2, h3 - g3);
                }
                *(uint4*)(Hh + t * PAD + qq * 8) = make_uint4(hv[0], hv[1], hv[2], hv[3]);
                *(uint4*)(Hl + t * PAD + qq * 8) = make_uint4(lv[0], lv[1], lv[2], lv[3]);
            }
        }
        __syncthreads();
#pragma unroll
        for (int ks = 0; ks < 2; ks++) {
            const int k0 = ks * 16;
            uint32_t ah[4][4], al[4][4], bh[4][2], bl[4][2];
#pragma unroll
            for (int mt = 0; mt < 4; mt++) {
                int ar = wm * 64 + mt * 16 + (lane & 15), ac = k0 + ((lane >> 4) << 3);
                ldm4(ah[mt], s2u(Hh + ar * PAD + ac));
                ldm4(al[mt], s2u(Hl + ar * PAD + ac));
            }
#pragma unroll
            for (int nh = 0; nh < 2; nh++) {
                int br = wn * 32 + nh * 16 + ((lane >> 4) << 3) + (lane & 7);
                int bc = k0 + (((lane >> 3) & 1) << 3);
                uint32_t r[4];
                ldm4(r, s2u(W2h + st * 2560 + br * PAD + bc));
                bh[nh*2][0]=r[0]; bh[nh*2][1]=r[1]; bh[nh*2+1][0]=r[2]; bh[nh*2+1][1]=r[3];
                ldm4(r, s2u(W2l + st * 2560 + br * PAD + bc));
                bl[nh*2][0]=r[0]; bl[nh*2][1]=r[1]; bl[nh*2+1][0]=r[2]; bl[nh*2+1][1]=r[3];
            }
#pragma unroll
            for (int mt = 0; mt < 4; mt++)
#pragma unroll
                for (int nt = 0; nt < 4; nt++) mma_bb(acc[mt][nt], ah[mt], bh[nt]);
#pragma unroll
            for (int mt = 0; mt < 4; mt++)
#pragma unroll
                for (int nt = 0; nt < 4; nt++) mma_bb(acc[mt][nt], ah[mt], bl[nt]);
#pragma unroll
            for (int mt = 0; mt < 4; mt++)
#pragma unroll
                for (int nt = 0; nt < 4; nt++) mma_bb(acc[mt][nt], al[mt], bh[nt]);
        }
        __syncthreads();
    }
#pragma unroll
    for (int mt = 0; mt < 4; mt++)
#pragma unroll
        for (int nt = 0; nt < 4; nt++) {
            int o = wn * 32 + nt * 8 + ((lane & 3) << 1);
            if (o < NR) {
                float bb0 = __ldg(&b2lab[o]), bb1 = __ldg(&b2lab[o + 1]);
#pragma unroll
                for (int half = 0; half < 2; half++) {
                    int pp = wm * 64 + mt * 16 + (lane >> 2) + half * 8;
                    int i = i0 + (pp >> 3), j = j0 + (pp & 7);
                    float2 v = make_float2(acc[mt][nt][half*2] + bb0,
                                           acc[mt][nt][half*2+1] + bb1);
                    *(float2*)&outl[((b * NS + i) * NS + j) * NR + o] = v;
                }
            }
        }
}

__global__ void sym_kernel(float* __restrict__ out) {
    int idx = blockIdx.x * 256 + threadIdx.x;
    int b = idx >> 14, r = idx & 16383, i = r >> 7, j = r & 127;
    if (i < j) out[idx] = out[(b << 14) + (j << 7) + i];
}

// ---------------------------------------------------------------------------
extern "C" void kernel_launch(void* const* d_in, const int* in_sizes, int n_in,
                              void* d_out, int out_size) {
    (void)in_sizes; (void)n_in; (void)out_size;
    const float* x = (const float*)d_in[0];
    ProjArgs pa;
    pa.W1[0] = (const float*)d_in[1];  pa.b1[0] = (const float*)d_in[2];
    pa.W1[1] = (const float*)d_in[5];  pa.b1[1] = (const float*)d_in[6];
    pa.W1[2] = (const float*)d_in[9];  pa.b1[2] = (const float*)d_in[10];
    pa.W1[3] = (const float*)d_in[13]; pa.b1[3] = (const float*)d_in[14];
    ScalArgs sa;
    sa.w2[0] = (const float*)d_in[3];  sa.b2[0] = (const float*)d_in[4];
    sa.w2[1] = (const float*)d_in[7];  sa.b2[1] = (const float*)d_in[8];
    sa.w2[2] = (const float*)d_in[11]; sa.b2[2] = (const float*)d_in[12];
    float* out = (float*)d_out;

    static int configured = 0;
    if (!configured) {
        cudaFuncSetAttribute(proj_mma, cudaFuncAttributeMaxDynamicSharedMemorySize,
                             2 * PJ_STAGE * (int)sizeof(__nv_bfloat16));
        cudaFuncSetAttribute(pairlab_kernel, cudaFuncAttributeMaxDynamicSharedMemorySize,
                             LAB_SMEM);
        configured = 1;
    }

    prep_x<<<2048, 256>>>(x);
    prep_w<<<dim3(16, 16, 8), 256>>>(pa);
    prep_w2<<<128, 256>>>((const float*)d_in[15]);

    proj_mma<<<dim3(8, 4, 8), 256, 2 * PJ_STAGE * (int)sizeof(__nv_bfloat16)>>>(pa);

    pairlab_kernel<<<dim3(16, 8, 7), 256, LAB_SMEM>>>(sa, (const float*)d_in[16], out);

    sym_kernel<<<512, 256>>>(out);
}